// round 8
// baseline (speedup 1.0000x reference)
#include <cuda_runtime.h>

typedef unsigned int u32;
typedef unsigned long long u64;

extern "C" __device__ float __nv_expf(float);   // libdevice expf (matches XLA)

#define K_TOP 4096
#define W_IMG 640
#define H_IMG 480
#define NPIX (W_IMG * H_IMG)      // 307200
#define WC 80
#define HC 60
#define NC (WC * HC)              // 4800
#define CH 64

#define OFF_KPTS  0
#define OFF_MATCH 16384
#define OFF_SCORE 20480
#define OFF_VALID 24576
#define OFF_H     28672
#define OFF_R     643072

__device__ float g_Hs[2 * NPIX];
__device__ float g_FS[2 * NPIX];
__device__ float g_nf[2 * CH * NC];
__device__ u32   g_hist[4][2][65536];
__device__ u64   g_prefix[2];
__device__ u32   g_krem[2];
__device__ u32   g_cnt[2];
__device__ u64   g_sel[2][K_TOP];
__device__ int   g_topidx[2][K_TOP];
__device__ float g_desc[2][K_TOP][CH];
__device__ u64   g_rowP[K_TOP];
__device__ u64   g_colP[K_TOP];

__device__ __forceinline__ u32 fkey(float f) {
    u32 u = __float_as_uint(f);
    return (u >> 31) ? ~u : (u | 0x80000000u);
}
__device__ __forceinline__ float unfkey(u32 k) {
    return __uint_as_float((k >> 31) ? (k & 0x7FFFFFFFu) : ~k);
}

__global__ void k_init() {
    int i = blockIdx.x * blockDim.x + threadIdx.x;
    int st = blockDim.x * gridDim.x;
    u32* h = &g_hist[0][0][0];
    for (int j = i; j < 4 * 2 * 65536; j += st) h[j] = 0;
    for (int j = i; j < K_TOP; j += st) { g_rowP[j] = 0ull; g_colP[j] = 0ull; }
    u64* sel = &g_sel[0][0];
    for (int j = i; j < 2 * K_TOP; j += st) sel[j] = 0ull;
    if (i < 2) { g_prefix[i] = 0ull; g_krem[i] = K_TOP; g_cnt[i] = 0; }
}

// softmax over 65 channels, XLA column-reduce order: lane partials over
// channels {l, l+32, lane0: 64} sequential, then shfl.down tree 16..1.
__global__ void k_shuffle(const float* __restrict__ logits) {
    int gw = (blockIdx.x * blockDim.x + threadIdx.x) >> 5;   // exact: 2*NC warps
    int lane = threadIdx.x & 31;
    int b = gw / NC, cell = gw % NC;
    int h = cell / WC, w = cell % WC;
    const float* p = logits + (size_t)b * 65 * NC + cell;
    float x0 = p[lane * NC];
    float x1 = p[(lane + 32) * NC];
    float x2 = (lane == 0) ? p[64 * NC] : __int_as_float(0xff800000);
    float m = fmaxf(fmaxf(x0, x1), x2);
    #pragma unroll
    for (int off = 16; off > 0; off >>= 1)
        m = fmaxf(m, __shfl_xor_sync(0xFFFFFFFFu, m, off));
    float e0 = __nv_expf(__fsub_rn(x0, m));
    float e1 = __nv_expf(__fsub_rn(x1, m));
    float e2 = __nv_expf(__fsub_rn(x2, m));   // exp(-inf)=0 for lane!=0
    float partial = __fadd_rn(__fadd_rn(e0, e1), e2);
    #pragma unroll
    for (int off = 16; off > 0; off >>= 1)
        partial = __fadd_rn(partial, __shfl_down_sync(0xFFFFFFFFu, partial, off));
    float s = __shfl_sync(0xFFFFFFFFu, partial, 0);
    float* out = g_Hs + (size_t)b * NPIX;
    int c0 = lane, c1 = lane + 32;
    out[(h * 8 + (c0 >> 3)) * W_IMG + (w * 8 + (c0 & 7))] = __fdiv_rn(e0, s);
    out[(h * 8 + (c1 >> 3)) * W_IMG + (w * 8 + (c1 & 7))] = __fdiv_rn(e1, s);
}

// feats norm, column-reduce association over 64 channels. One warp/pixel.
__global__ void k_normfeats(const float* __restrict__ feats) {
    int gw = (blockIdx.x * blockDim.x + threadIdx.x) >> 5;   // exact: 2*NC warps
    int lane = threadIdx.x & 31;
    int b = gw / NC, p = gw % NC;
    const float* f = feats + (size_t)b * CH * NC + p;
    float* o = g_nf + (size_t)b * CH * NC + p;
    float x0 = f[lane * NC];
    float x1 = f[(lane + 32) * NC];
    float partial = __fadd_rn(__fmul_rn(x0, x0), __fmul_rn(x1, x1));
    #pragma unroll
    for (int off = 16; off > 0; off >>= 1)
        partial = __fadd_rn(partial, __shfl_down_sync(0xFFFFFFFFu, partial, off));
    float s = __shfl_sync(0xFFFFFFFFu, partial, 0);
    float n = fmaxf(__fsqrt_rn(s), 1e-12f);
    o[lane * NC] = __fdiv_rn(x0, n);
    o[(lane + 32) * NC] = __fdiv_rn(x1, n);
}

// 5x5 NMS + bilinear reliability (W-then-H fma chains, exact clamped weights)
__global__ void k_nms(const float* __restrict__ heatmap, float* __restrict__ dout) {
    int gid = blockIdx.x * blockDim.x + threadIdx.x;   // exact: 2*NPIX
    int b = gid / NPIX, p = gid % NPIX;
    int oy = p / W_IMG, ox = p % W_IMG;

    float sy = __fsub_rn(__fmul_rn(__fadd_rn((float)oy, 0.5f), 0.125f), 0.5f);
    float sx = __fsub_rn(__fmul_rn(__fadd_rn((float)ox, 0.5f), 0.125f), 0.5f);
    int iy0 = (int)floorf(sy);
    int ix0 = (int)floorf(sx);
    float fy = __fsub_rn(sy, (float)iy0);
    float fx = __fsub_rn(sx, (float)ix0);
    int y0 = iy0 < 0 ? 0 : iy0;
    int y1 = iy0 >= HC - 1 ? HC - 1 : iy0 + 1;
    int x0 = ix0 < 0 ? 0 : ix0;
    int x1 = ix0 >= WC - 1 ? WC - 1 : ix0 + 1;
    float wy0 = iy0 < 0 ? 0.f : (iy0 >= HC - 1 ? 1.f : __fsub_rn(1.f, fy));
    float wy1 = iy0 < 0 ? 1.f : (iy0 >= HC - 1 ? 0.f : fy);
    float wx0 = ix0 < 0 ? 0.f : (ix0 >= WC - 1 ? 1.f : __fsub_rn(1.f, fx));
    float wx1 = ix0 < 0 ? 1.f : (ix0 >= WC - 1 ? 0.f : fx);
    const float* hm = heatmap + (size_t)b * NC;
    float t0 = __fmaf_rn(wx1, hm[y0 * WC + x1], __fmul_rn(wx0, hm[y0 * WC + x0]));
    float t1 = __fmaf_rn(wx1, hm[y1 * WC + x1], __fmul_rn(wx0, hm[y1 * WC + x0]));
    float rel = __fmaf_rn(wy1, t1, __fmul_rn(wy0, t0));

    const float* Hs = g_Hs + (size_t)b * NPIX;
    float x = Hs[p];
    float lm = x;
    #pragma unroll
    for (int dy = -2; dy <= 2; dy++) {
        int yy = oy + dy;
        if ((unsigned)yy >= H_IMG) continue;
        #pragma unroll
        for (int dx = -2; dx <= 2; dx++) {
            int xx = ox + dx;
            if ((unsigned)xx >= W_IMG) continue;
            lm = fmaxf(lm, __ldg(&Hs[yy * W_IMG + xx]));
        }
    }
    float fs = (x == lm) ? __fmul_rn(x, rel) : 0.f;
    if (fs == 0.f) fs = 0.f;   // canonicalize -0 for keying
    g_FS[gid] = fs;
    dout[OFF_H + gid] = fs;
    dout[OFF_R + gid] = rel;
}

// top-K: 64-bit radix select, 4 x 16-bit levels
template <int L>
__global__ void k_hist() {
    int gid = blockIdx.x * blockDim.x + threadIdx.x;   // exact: 2*NPIX
    int b = gid / NPIX;
    u32 i = gid % NPIX;
    u64 key = ((u64)fkey(g_FS[gid]) << 32) | (u64)(0xFFFFFFFFu - i);
    bool act = true;
    if (L > 0) act = ((key >> (u32)(64 - 16 * L)) == g_prefix[b]);
    u32 bin = (u32)(key >> (u32)(48 - 16 * L)) & 0xFFFFu;
    u32 m = __ballot_sync(0xFFFFFFFFu, act);
    if (act) {
        u32 peers = __match_any_sync(m, bin);
        if ((u32)(__ffs(peers) - 1) == (threadIdx.x & 31u))
            atomicAdd(&g_hist[L][b][bin], __popc(peers));
    }
}

template <int L>
__global__ void k_scan() {
    int b = blockIdx.x;
    const u32* h = g_hist[L][b];
    __shared__ u32 part[256];
    int t = threadIdx.x;
    u32 s = 0;
    for (int i = 0; i < 256; i++) s += h[t * 256 + i];
    part[t] = s;
    __syncthreads();
    if (t == 0) {
        u32 krem = g_krem[b], acc = 0;
        int c = 255;
        for (; c > 0; c--) { if (acc + part[c] >= krem) break; acc += part[c]; }
        int v = c * 256 + 255;
        for (; v > c * 256; v--) { u32 cv = h[v]; if (acc + cv >= krem) break; acc += cv; }
        g_krem[b] = krem - acc;
        g_prefix[b] = (g_prefix[b] << 16) | (u64)(u32)v;
    }
}

__global__ void k_compact() {
    int gid = blockIdx.x * blockDim.x + threadIdx.x;   // exact: 2*NPIX
    int b = gid / NPIX;
    u32 i = gid % NPIX;
    u64 key = ((u64)fkey(g_FS[gid]) << 32) | (u64)(0xFFFFFFFFu - i);
    if (key >= g_prefix[b]) {
        u32 pos = atomicAdd(&g_cnt[b], 1);
        if (pos < K_TOP) g_sel[b][pos] = key;
    }
}

__global__ void k_sort(float* __restrict__ dout) {
    __shared__ u64 s[K_TOP];
    int b = blockIdx.x;
    for (int i = threadIdx.x; i < K_TOP; i += 1024) s[i] = g_sel[b][i];
    __syncthreads();
    for (int k2 = 2; k2 <= K_TOP; k2 <<= 1) {
        for (int j = k2 >> 1; j > 0; j >>= 1) {
            for (int i = threadIdx.x; i < K_TOP; i += 1024) {
                int ixj = i ^ j;
                if (ixj > i) {
                    u64 a = s[i], c = s[ixj];
                    bool up = ((i & k2) == 0);
                    if (up ? (a < c) : (a > c)) { s[i] = c; s[ixj] = a; }
                }
            }
            __syncthreads();
        }
    }
    for (int r = threadIdx.x; r < K_TOP; r += 1024) {
        u32 idx = 0xFFFFFFFFu - (u32)s[r];
        g_topidx[b][r] = (int)idx;
        float x = (float)(idx % W_IMG), y = (float)(idx / W_IMG);
        dout[OFF_KPTS + (size_t)b * K_TOP * 2 + r * 2 + 0] = x;
        dout[OFF_KPTS + (size_t)b * K_TOP * 2 + r * 2 + 1] = y;
    }
}

// grid-sample + renorm; norm = row-reduce (vectorized x2): lane l owns
// contiguous channels {2l, 2l+1}, partial = x0^2 + x1^2, then shfl.down tree.
__global__ void k_desc() {
    int k = blockIdx.x, b = blockIdx.y, lane = threadIdx.x;   // 32 threads
    int idx = g_topidx[b][k];
    float xf = (float)(idx % W_IMG), yf = (float)(idx / W_IMG);
    float gx = __fsub_rn(__fmul_rn(__fdiv_rn(xf, 639.f), 2.f), 1.f);
    float gy = __fsub_rn(__fmul_rn(__fdiv_rn(yf, 479.f), 2.f), 1.f);
    float ix = __fmul_rn(__fmul_rn(__fadd_rn(gx, 1.f), 0.5f), 79.f);
    float iy = __fmul_rn(__fmul_rn(__fadd_rn(gy, 1.f), 0.5f), 59.f);
    float ix0f = floorf(ix), iy0f = floorf(iy);
    float wx = __fsub_rn(ix, ix0f), wy = __fsub_rn(iy, iy0f);
    float omx = __fsub_rn(1.f, wx), omy = __fsub_rn(1.f, wy);
    int x0 = min(max((int)ix0f, 0), WC - 1), y0 = min(max((int)iy0f, 0), HC - 1);
    int x1 = min(x0 + 1, WC - 1), y1 = min(y0 + 1, HC - 1);
    int p00 = y0 * WC + x0, p01 = y0 * WC + x1, p10 = y1 * WC + x0, p11 = y1 * WC + x1;
    float v[2];
    #pragma unroll
    for (int t = 0; t < 2; t++) {
        int c = 2 * lane + t;
        const float* f = g_nf + ((size_t)b * CH + c) * NC;
        float t1 = __fmul_rn(__fmul_rn(f[p00], omx), omy);
        float t2 = __fmul_rn(__fmul_rn(f[p01], wx), omy);
        float t3 = __fmul_rn(__fmul_rn(f[p10], omx), wy);
        float t4 = __fmul_rn(__fmul_rn(f[p11], wx), wy);
        v[t] = __fadd_rn(__fadd_rn(__fadd_rn(t1, t2), t3), t4);
    }
    float pr = __fadd_rn(__fmul_rn(v[0], v[0]), __fmul_rn(v[1], v[1]));
    #pragma unroll
    for (int off = 16; off > 0; off >>= 1)
        pr = __fadd_rn(pr, __shfl_down_sync(0xFFFFFFFFu, pr, off));
    float n = fmaxf(__fsqrt_rn(__shfl_sync(0xFFFFFFFFu, pr, 0)), 1e-12f);
    g_desc[b][k][2 * lane + 0] = __fdiv_rn(v[0], n);
    g_desc[b][k][2 * lane + 1] = __fdiv_rn(v[1], n);
}

// sim = desc0 @ desc1^T in plain FP32: per-output single accumulator,
// ascending-k FFMA chain from 0 (cuBLAS SGEMM association). Fused argmax.
#define TS 128
__global__ void k_sim() {
    extern __shared__ float sh[];
    float* As = sh;             // [64][128] k-major
    float* Bs = sh + 64 * TS;   // [64][128] k-major
    int tid = threadIdx.x;
    int rb = blockIdx.y * TS;
    int cb = blockIdx.x * TS;
    const float4* d0 = (const float4*)&g_desc[0][0][0];
    const float4* d1 = (const float4*)&g_desc[1][0][0];
    for (int t = tid; t < TS * 16; t += 256) {
        int r = t >> 4, c4 = t & 15;
        float4 a = d0[(size_t)(rb + r) * 16 + c4];
        As[(c4 * 4 + 0) * TS + r] = a.x; As[(c4 * 4 + 1) * TS + r] = a.y;
        As[(c4 * 4 + 2) * TS + r] = a.z; As[(c4 * 4 + 3) * TS + r] = a.w;
        float4 bv = d1[(size_t)(cb + r) * 16 + c4];
        Bs[(c4 * 4 + 0) * TS + r] = bv.x; Bs[(c4 * 4 + 1) * TS + r] = bv.y;
        Bs[(c4 * 4 + 2) * TS + r] = bv.z; Bs[(c4 * 4 + 3) * TS + r] = bv.w;
    }
    __syncthreads();
    int tx = tid & 15, ty = tid >> 4;
    float acc[8][8];
    #pragma unroll
    for (int i = 0; i < 8; i++)
        #pragma unroll
        for (int j = 0; j < 8; j++) acc[i][j] = 0.f;
    #pragma unroll 4
    for (int kk = 0; kk < 64; kk++) {     // strictly ascending k
        const float* Ak = As + kk * TS;
        const float* Bk = Bs + kk * TS;
        float4 a0 = *(const float4*)(Ak + ty * 4);
        float4 a1 = *(const float4*)(Ak + 64 + ty * 4);
        float4 b0 = *(const float4*)(Bk + tx * 4);
        float4 b1 = *(const float4*)(Bk + 64 + tx * 4);
        float av[8] = {a0.x, a0.y, a0.z, a0.w, a1.x, a1.y, a1.z, a1.w};
        float bv[8] = {b0.x, b0.y, b0.z, b0.w, b1.x, b1.y, b1.z, b1.w};
        #pragma unroll
        for (int i = 0; i < 8; i++)
            #pragma unroll
            for (int j = 0; j < 8; j++)
                acc[i][j] = __fmaf_rn(av[i], bv[j], acc[i][j]);
    }
    __syncthreads();
    u64* rowP = (u64*)sh;
    u64* colP = rowP + TS;
    if (tid < TS) { rowP[tid] = 0ull; colP[tid] = 0ull; }
    __syncthreads();
    #pragma unroll
    for (int i = 0; i < 8; i++) {
        int lr = (i < 4) ? (ty * 4 + i) : (64 + ty * 4 + i - 4);
        u64 best = 0ull;
        #pragma unroll
        for (int j = 0; j < 8; j++) {
            int gc = cb + ((j < 4) ? (tx * 4 + j) : (64 + tx * 4 + j - 4));
            u64 pk = ((u64)fkey(acc[i][j]) << 32) | (u64)(0xFFFFFFFFu - (u32)gc);
            if (pk > best) best = pk;
        }
        atomicMax(&rowP[lr], best);
    }
    #pragma unroll
    for (int j = 0; j < 8; j++) {
        int lc = (j < 4) ? (tx * 4 + j) : (64 + tx * 4 + j - 4);
        u64 best = 0ull;
        #pragma unroll
        for (int i = 0; i < 8; i++) {
            int gr = rb + ((i < 4) ? (ty * 4 + i) : (64 + ty * 4 + i - 4));
            u64 pk = ((u64)fkey(acc[i][j]) << 32) | (u64)(0xFFFFFFFFu - (u32)gr);
            if (pk > best) best = pk;
        }
        atomicMax(&colP[lc], best);
    }
    __syncthreads();
    if (tid < TS) {
        atomicMax(&g_rowP[rb + tid], rowP[tid]);
        atomicMax(&g_colP[cb + tid], colP[tid]);
    }
}

__global__ void k_final(float* __restrict__ dout) {
    int k = blockIdx.x * blockDim.x + threadIdx.x;   // exact: 4096
    u64 rp = g_rowP[k];
    float sc = unfkey((u32)(rp >> 32));
    u32 m01 = 0xFFFFFFFFu - (u32)rp;
    u64 cp = g_colP[m01];
    u32 m10 = 0xFFFFFFFFu - (u32)cp;
    bool valid = (m10 == (u32)k) && (sc > 0.1f);
    dout[OFF_MATCH + k] = (float)m01;
    dout[OFF_SCORE + k] = sc;
    dout[OFF_VALID + k] = valid ? 1.f : 0.f;
}

extern "C" void kernel_launch(void* const* d_in, const int* in_sizes, int n_in,
                              void* d_out, int out_size) {
    const float* feats   = (const float*)d_in[0];
    const float* logits  = (const float*)d_in[1];
    const float* heatmap = (const float*)d_in[2];
    float* out = (float*)d_out;

    cudaFuncSetAttribute(k_sim, cudaFuncAttributeMaxDynamicSharedMemorySize, 64 * TS * 2 * 4);

    k_init<<<256, 256>>>();
    k_shuffle<<<1200, 256>>>(logits);          // 9600 warps: one per cell
    k_normfeats<<<1200, 256>>>(feats);         // 9600 warps: one per pixel
    k_nms<<<2 * NPIX / 256, 256>>>(heatmap, out);
    k_hist<0><<<2 * NPIX / 256, 256>>>(); k_scan<0><<<2, 256>>>();
    k_hist<1><<<2 * NPIX / 256, 256>>>(); k_scan<1><<<2, 256>>>();
    k_hist<2><<<2 * NPIX / 256, 256>>>(); k_scan<2><<<2, 256>>>();
    k_hist<3><<<2 * NPIX / 256, 256>>>(); k_scan<3><<<2, 256>>>();
    k_compact<<<2 * NPIX / 256, 256>>>();
    k_sort<<<2, 1024>>>(out);
    k_desc<<<dim3(K_TOP, 2), 32>>>();
    k_sim<<<dim3(K_TOP / TS, K_TOP / TS), 256, 64 * TS * 2 * 4>>>();
    k_final<<<K_TOP / 256, 256>>>(out);
}

// round 9
// speedup vs baseline: 1.0327x; 1.0327x over previous
#include <cuda_runtime.h>

typedef unsigned int u32;
typedef unsigned long long u64;

extern "C" __device__ float __nv_expf(float);   // libdevice expf (matches XLA)

#define K_TOP 4096
#define W_IMG 640
#define H_IMG 480
#define NPIX (W_IMG * H_IMG)      // 307200
#define WC 80
#define HC 60
#define NC (WC * HC)              // 4800
#define CH 64
#define CAND_MAX 320000

#define OFF_KPTS  0
#define OFF_MATCH 16384
#define OFF_SCORE 20480
#define OFF_VALID 24576
#define OFF_H     28672
#define OFF_R     643072

__device__ float g_Hs[2 * NPIX];
__device__ float g_FS[2 * NPIX];
__device__ float g_nf[2 * CH * NC];
__device__ u32   g_hist[4][2][65536];
__device__ u64   g_prefix[2];
__device__ u32   g_krem[2];
__device__ u32   g_cnt[2];
__device__ u32   g_candn[2][2];
__device__ u64   g_cand[2][2][CAND_MAX];
__device__ u64   g_sel[2][K_TOP];
__device__ int   g_topidx[2][K_TOP];
__device__ float g_desc[2][K_TOP][CH];
__device__ u64   g_rowP[K_TOP];
__device__ u64   g_colP[K_TOP];

__device__ __forceinline__ u32 fkey(float f) {
    u32 u = __float_as_uint(f);
    return (u >> 31) ? ~u : (u | 0x80000000u);
}
__device__ __forceinline__ float unfkey(u32 k) {
    return __uint_as_float((k >> 31) ? (k & 0x7FFFFFFFu) : ~k);
}

// warp-aggregated append: returns position for this thread (call with active pred)
__device__ __forceinline__ u32 warp_append(u32* counter, u32 mask) {
    int lane = threadIdx.x & 31;
    u32 ldr = __ffs(mask) - 1;
    u32 base = 0;
    if ((u32)lane == ldr) base = atomicAdd(counter, __popc(mask));
    base = __shfl_sync(mask, base, ldr);
    return base + __popc(mask & ((1u << lane) - 1));
}

__global__ void k_init() {
    int i = blockIdx.x * blockDim.x + threadIdx.x;
    int st = blockDim.x * gridDim.x;
    u32* h = &g_hist[0][0][0];
    for (int j = i; j < 4 * 2 * 65536; j += st) h[j] = 0;
    for (int j = i; j < K_TOP; j += st) { g_rowP[j] = 0ull; g_colP[j] = 0ull; }
    if (i < 2) {
        g_prefix[i] = 0ull; g_krem[i] = K_TOP; g_cnt[i] = 0;
        g_candn[i][0] = 0; g_candn[i][1] = 0;
    }
}

// softmax over 65 channels (XLA column-reduce order), smem-staged coalesced.
// Block = 256 threads, 64 cells; identical arithmetic to validated version.
__global__ void k_shuffle(const float* __restrict__ logits) {
    __shared__ float ls[65 * 65];    // [ch][cell], pad 65 (conflict-free)
    int blk = blockIdx.x;            // 150 blocks
    int b = blk / 75;
    int cellbase = (blk % 75) * 64;
    const float* p = logits + (size_t)b * 65 * NC + cellbase;
    for (int i = threadIdx.x; i < 65 * 64; i += 256) {
        int ch = i >> 6, cl = i & 63;
        ls[ch * 65 + cl] = p[ch * NC + cl];
    }
    __syncthreads();
    int lane = threadIdx.x & 31, wrp = threadIdx.x >> 5;
    float* out = g_Hs + (size_t)b * NPIX;
    #pragma unroll
    for (int s = 0; s < 8; s++) {
        int cell = wrp * 8 + s;
        float x0 = ls[lane * 65 + cell];
        float x1 = ls[(lane + 32) * 65 + cell];
        float x2 = (lane == 0) ? ls[64 * 65 + cell] : __int_as_float(0xff800000);
        float m = fmaxf(fmaxf(x0, x1), x2);
        #pragma unroll
        for (int off = 16; off > 0; off >>= 1)
            m = fmaxf(m, __shfl_xor_sync(0xFFFFFFFFu, m, off));
        float e0 = __nv_expf(__fsub_rn(x0, m));
        float e1 = __nv_expf(__fsub_rn(x1, m));
        float e2 = __nv_expf(__fsub_rn(x2, m));   // exp(-inf)=0 for lane!=0
        float partial = __fadd_rn(__fadd_rn(e0, e1), e2);
        #pragma unroll
        for (int off = 16; off > 0; off >>= 1)
            partial = __fadd_rn(partial, __shfl_down_sync(0xFFFFFFFFu, partial, off));
        float ssum = __shfl_sync(0xFFFFFFFFu, partial, 0);
        int gcell = cellbase + cell;
        int h = gcell / WC, w = gcell % WC;
        int c0 = lane, c1 = lane + 32;
        out[(h * 8 + (c0 >> 3)) * W_IMG + (w * 8 + (c0 & 7))] = __fdiv_rn(e0, ssum);
        out[(h * 8 + (c1 >> 3)) * W_IMG + (w * 8 + (c1 & 7))] = __fdiv_rn(e1, ssum);
    }
}

// feats norm (column-reduce association), smem-staged coalesced read+write.
__global__ void k_normfeats(const float* __restrict__ feats) {
    __shared__ float fsm[64 * 65];
    __shared__ float nrm[64];
    int blk = blockIdx.x;            // 150 blocks
    int b = blk / 75;
    int cellbase = (blk % 75) * 64;
    const float* f = feats + (size_t)b * CH * NC + cellbase;
    float* o = g_nf + (size_t)b * CH * NC + cellbase;
    for (int i = threadIdx.x; i < 64 * 64; i += 256) {
        int ch = i >> 6, cl = i & 63;
        fsm[ch * 65 + cl] = f[ch * NC + cl];
    }
    __syncthreads();
    int lane = threadIdx.x & 31, wrp = threadIdx.x >> 5;
    #pragma unroll
    for (int s = 0; s < 8; s++) {
        int cell = wrp * 8 + s;
        float x0 = fsm[lane * 65 + cell];
        float x1 = fsm[(lane + 32) * 65 + cell];
        float partial = __fadd_rn(__fmul_rn(x0, x0), __fmul_rn(x1, x1));
        #pragma unroll
        for (int off = 16; off > 0; off >>= 1)
            partial = __fadd_rn(partial, __shfl_down_sync(0xFFFFFFFFu, partial, off));
        if (lane == 0) nrm[cell] = fmaxf(__fsqrt_rn(partial), 1e-12f);
    }
    __syncthreads();
    for (int i = threadIdx.x; i < 64 * 64; i += 256) {
        int ch = i >> 6, cl = i & 63;
        o[ch * NC + cl] = __fdiv_rn(fsm[ch * 65 + cl], nrm[cl]);
    }
}

// 5x5 NMS + bilinear reliability + FUSED level-0 histogram (hi-16 of fkey)
__global__ void k_nms(const float* __restrict__ heatmap, float* __restrict__ dout) {
    int gid = blockIdx.x * blockDim.x + threadIdx.x;   // exact: 2*NPIX
    int b = gid / NPIX, p = gid % NPIX;
    int oy = p / W_IMG, ox = p % W_IMG;

    float sy = __fsub_rn(__fmul_rn(__fadd_rn((float)oy, 0.5f), 0.125f), 0.5f);
    float sx = __fsub_rn(__fmul_rn(__fadd_rn((float)ox, 0.5f), 0.125f), 0.5f);
    int iy0 = (int)floorf(sy);
    int ix0 = (int)floorf(sx);
    float fy = __fsub_rn(sy, (float)iy0);
    float fx = __fsub_rn(sx, (float)ix0);
    int y0 = iy0 < 0 ? 0 : iy0;
    int y1 = iy0 >= HC - 1 ? HC - 1 : iy0 + 1;
    int x0 = ix0 < 0 ? 0 : ix0;
    int x1 = ix0 >= WC - 1 ? WC - 1 : ix0 + 1;
    float wy0 = iy0 < 0 ? 0.f : (iy0 >= HC - 1 ? 1.f : __fsub_rn(1.f, fy));
    float wy1 = iy0 < 0 ? 1.f : (iy0 >= HC - 1 ? 0.f : fy);
    float wx0 = ix0 < 0 ? 0.f : (ix0 >= WC - 1 ? 1.f : __fsub_rn(1.f, fx));
    float wx1 = ix0 < 0 ? 1.f : (ix0 >= WC - 1 ? 0.f : fx);
    const float* hm = heatmap + (size_t)b * NC;
    float t0 = __fmaf_rn(wx1, hm[y0 * WC + x1], __fmul_rn(wx0, hm[y0 * WC + x0]));
    float t1 = __fmaf_rn(wx1, hm[y1 * WC + x1], __fmul_rn(wx0, hm[y1 * WC + x0]));
    float rel = __fmaf_rn(wy1, t1, __fmul_rn(wy0, t0));

    const float* Hs = g_Hs + (size_t)b * NPIX;
    float x = Hs[p];
    float lm = x;
    #pragma unroll
    for (int dy = -2; dy <= 2; dy++) {
        int yy = oy + dy;
        if ((unsigned)yy >= H_IMG) continue;
        #pragma unroll
        for (int dx = -2; dx <= 2; dx++) {
            int xx = ox + dx;
            if ((unsigned)xx >= W_IMG) continue;
            lm = fmaxf(lm, __ldg(&Hs[yy * W_IMG + xx]));
        }
    }
    float fs = (x == lm) ? __fmul_rn(x, rel) : 0.f;
    if (fs == 0.f) fs = 0.f;   // canonicalize -0
    g_FS[gid] = fs;
    dout[OFF_H + gid] = fs;
    dout[OFF_R + gid] = rel;

    // level-0 histogram (b uniform within block)
    u32 bin = fkey(fs) >> 16;
    u32 peers = __match_any_sync(0xFFFFFFFFu, bin);
    if ((u32)(__ffs(peers) - 1) == (threadIdx.x & 31u))
        atomicAdd(&g_hist[0][b][bin], __popc(peers));
}

template <int L>
__global__ void k_scan() {
    int b = blockIdx.x;
    const u32* h = g_hist[L][b];
    __shared__ u32 part[256];
    int t = threadIdx.x;
    u32 s = 0;
    for (int i = 0; i < 256; i++) s += h[t * 256 + i];
    part[t] = s;
    __syncthreads();
    if (t == 0) {
        u32 krem = g_krem[b], acc = 0;
        int c = 255;
        for (; c > 0; c--) { if (acc + part[c] >= krem) break; acc += part[c]; }
        int v = c * 256 + 255;
        for (; v > c * 256; v--) { u32 cv = h[v]; if (acc + cv >= krem) break; acc += cv; }
        g_krem[b] = krem - acc;
        g_prefix[b] = (g_prefix[b] << 16) | (u64)(u32)v;
        if (L == 2) g_candn[b][0] = 0;   // recycle buffer 0 for level-2 output
    }
}

// full pass: definite keys -> g_sel; threshold-bin keys -> cand[0] + hist[1]
__global__ void k_sel0() {
    int gid = blockIdx.x * blockDim.x + threadIdx.x;   // exact: 2*NPIX
    int b = gid / NPIX;
    u32 i = gid % NPIX;
    u64 key = ((u64)fkey(g_FS[gid]) << 32) | (u64)(0xFFFFFFFFu - i);
    u32 v0 = (u32)(g_prefix[b] & 0xFFFFu);
    u32 bin = (u32)(key >> 48);
    bool isDef = bin > v0, isCand = bin == v0;
    u32 md = __ballot_sync(0xFFFFFFFFu, isDef);
    if (isDef) {
        u32 pos = warp_append(&g_cnt[b], md);
        if (pos < K_TOP) g_sel[b][pos] = key;
    }
    u32 mc = __ballot_sync(0xFFFFFFFFu, isCand);
    if (isCand) {
        u32 pos = warp_append(&g_candn[b][0], mc);
        if (pos < CAND_MAX) g_cand[b][0][pos] = key;
        u32 bin2 = (u32)(key >> 32) & 0xFFFFu;
        u32 peers = __match_any_sync(mc, bin2);
        if ((u32)(__ffs(peers) - 1) == (threadIdx.x & 31u))
            atomicAdd(&g_hist[1][b][bin2], __popc(peers));
    }
}

// levels 1,2 over candidate buffers (src = LVL&1^1 mapping below)
template <int LVL>   // 1: src0->dst1, hist2 ; 2: src1->dst0, hist3
__global__ void k_selmid() {
    int b = blockIdx.y;
    const int src = (LVL == 1) ? 0 : 1;
    const int dst = 1 - src;
    u32 N = g_candn[b][src];
    u32 vL = (u32)(g_prefix[b] & 0xFFFFu);
    const int shift = 48 - 16 * LVL;
    u32 total = (N + 255u) & ~255u;
    u32 t0 = blockIdx.x * blockDim.x + threadIdx.x;
    u32 stride = gridDim.x * blockDim.x;
    for (u32 t = t0; t < total; t += stride) {
        bool valid = t < N;
        u64 key = valid ? g_cand[b][src][t] : 0ull;
        u32 bin = (u32)(key >> shift) & 0xFFFFu;
        bool isDef = valid && (bin > vL);
        bool isCand = valid && (bin == vL);
        u32 md = __ballot_sync(0xFFFFFFFFu, isDef);
        if (isDef) {
            u32 pos = warp_append(&g_cnt[b], md);
            if (pos < K_TOP) g_sel[b][pos] = key;
        }
        u32 mc = __ballot_sync(0xFFFFFFFFu, isCand);
        if (isCand) {
            u32 pos = warp_append(&g_candn[b][dst], mc);
            if (pos < CAND_MAX) g_cand[b][dst][pos] = key;
            u32 binN = (u32)(key >> (shift - 16)) & 0xFFFFu;
            u32 peers = __match_any_sync(mc, binN);
            if ((u32)(__ffs(peers) - 1) == (threadIdx.x & 31u))
                atomicAdd(&g_hist[LVL + 1][b][binN], __popc(peers));
        }
    }
}

// level 3: bins unique per key -> bin >= v3 all definite (fills exactly K)
__global__ void k_sel3() {
    int b = blockIdx.y;
    u32 N = g_candn[b][0];
    u32 v3 = (u32)(g_prefix[b] & 0xFFFFu);
    u32 total = (N + 255u) & ~255u;
    u32 t0 = blockIdx.x * blockDim.x + threadIdx.x;
    u32 stride = gridDim.x * blockDim.x;
    for (u32 t = t0; t < total; t += stride) {
        bool valid = t < N;
        u64 key = valid ? g_cand[b][0][t] : 0ull;
        bool isDef = valid && (((u32)key & 0xFFFFu) >= v3);
        u32 md = __ballot_sync(0xFFFFFFFFu, isDef);
        if (isDef) {
            u32 pos = warp_append(&g_cnt[b], md);
            if (pos < K_TOP) g_sel[b][pos] = key;
        }
    }
}

// rank-by-counting (keys unique): rank = #{keys greater}; emit kpts + topidx
__global__ void k_rank(float* __restrict__ dout) {
    int b = blockIdx.y;
    int i = blockIdx.x * 256 + threadIdx.x;   // 16 x 2 blocks
    u64 my = g_sel[b][i];
    __shared__ u64 tile[256];
    int r = 0;
    for (int t = 0; t < K_TOP; t += 256) {
        tile[threadIdx.x] = g_sel[b][t + threadIdx.x];
        __syncthreads();
        #pragma unroll 8
        for (int j = 0; j < 256; j++) r += (tile[j] > my);
        __syncthreads();
    }
    u32 idx = 0xFFFFFFFFu - (u32)my;
    g_topidx[b][r] = (int)idx;
    float x = (float)(idx % W_IMG), y = (float)(idx / W_IMG);
    dout[OFF_KPTS + (size_t)b * K_TOP * 2 + r * 2 + 0] = x;
    dout[OFF_KPTS + (size_t)b * K_TOP * 2 + r * 2 + 1] = y;
}

// grid-sample + renorm (row-reduce x2 association) — unchanged
__global__ void k_desc() {
    int k = blockIdx.x, b = blockIdx.y, lane = threadIdx.x;   // 32 threads
    int idx = g_topidx[b][k];
    float xf = (float)(idx % W_IMG), yf = (float)(idx / W_IMG);
    float gx = __fsub_rn(__fmul_rn(__fdiv_rn(xf, 639.f), 2.f), 1.f);
    float gy = __fsub_rn(__fmul_rn(__fdiv_rn(yf, 479.f), 2.f), 1.f);
    float ix = __fmul_rn(__fmul_rn(__fadd_rn(gx, 1.f), 0.5f), 79.f);
    float iy = __fmul_rn(__fmul_rn(__fadd_rn(gy, 1.f), 0.5f), 59.f);
    float ix0f = floorf(ix), iy0f = floorf(iy);
    float wx = __fsub_rn(ix, ix0f), wy = __fsub_rn(iy, iy0f);
    float omx = __fsub_rn(1.f, wx), omy = __fsub_rn(1.f, wy);
    int x0 = min(max((int)ix0f, 0), WC - 1), y0 = min(max((int)iy0f, 0), HC - 1);
    int x1 = min(x0 + 1, WC - 1), y1 = min(y0 + 1, HC - 1);
    int p00 = y0 * WC + x0, p01 = y0 * WC + x1, p10 = y1 * WC + x0, p11 = y1 * WC + x1;
    float v[2];
    #pragma unroll
    for (int t = 0; t < 2; t++) {
        int c = 2 * lane + t;
        const float* f = g_nf + ((size_t)b * CH + c) * NC;
        float t1 = __fmul_rn(__fmul_rn(f[p00], omx), omy);
        float t2 = __fmul_rn(__fmul_rn(f[p01], wx), omy);
        float t3 = __fmul_rn(__fmul_rn(f[p10], omx), wy);
        float t4 = __fmul_rn(__fmul_rn(f[p11], wx), wy);
        v[t] = __fadd_rn(__fadd_rn(__fadd_rn(t1, t2), t3), t4);
    }
    float pr = __fadd_rn(__fmul_rn(v[0], v[0]), __fmul_rn(v[1], v[1]));
    #pragma unroll
    for (int off = 16; off > 0; off >>= 1)
        pr = __fadd_rn(pr, __shfl_down_sync(0xFFFFFFFFu, pr, off));
    float n = fmaxf(__fsqrt_rn(__shfl_sync(0xFFFFFFFFu, pr, 0)), 1e-12f);
    g_desc[b][k][2 * lane + 0] = __fdiv_rn(v[0], n);
    g_desc[b][k][2 * lane + 1] = __fdiv_rn(v[1], n);
}

// sim: VALIDATED fp32 ascending-k FFMA chain; fused row/col argmax. UNCHANGED.
#define TS 128
__global__ void k_sim() {
    extern __shared__ float sh[];
    float* As = sh;             // [64][128] k-major
    float* Bs = sh + 64 * TS;   // [64][128] k-major
    int tid = threadIdx.x;
    int rb = blockIdx.y * TS;
    int cb = blockIdx.x * TS;
    const float4* d0 = (const float4*)&g_desc[0][0][0];
    const float4* d1 = (const float4*)&g_desc[1][0][0];
    for (int t = tid; t < TS * 16; t += 256) {
        int r = t >> 4, c4 = t & 15;
        float4 a = d0[(size_t)(rb + r) * 16 + c4];
        As[(c4 * 4 + 0) * TS + r] = a.x; As[(c4 * 4 + 1) * TS + r] = a.y;
        As[(c4 * 4 + 2) * TS + r] = a.z; As[(c4 * 4 + 3) * TS + r] = a.w;
        float4 bv = d1[(size_t)(cb + r) * 16 + c4];
        Bs[(c4 * 4 + 0) * TS + r] = bv.x; Bs[(c4 * 4 + 1) * TS + r] = bv.y;
        Bs[(c4 * 4 + 2) * TS + r] = bv.z; Bs[(c4 * 4 + 3) * TS + r] = bv.w;
    }
    __syncthreads();
    int tx = tid & 15, ty = tid >> 4;
    float acc[8][8];
    #pragma unroll
    for (int i = 0; i < 8; i++)
        #pragma unroll
        for (int j = 0; j < 8; j++) acc[i][j] = 0.f;
    #pragma unroll 4
    for (int kk = 0; kk < 64; kk++) {     // strictly ascending k
        const float* Ak = As + kk * TS;
        const float* Bk = Bs + kk * TS;
        float4 a0 = *(const float4*)(Ak + ty * 4);
        float4 a1 = *(const float4*)(Ak + 64 + ty * 4);
        float4 b0 = *(const float4*)(Bk + tx * 4);
        float4 b1 = *(const float4*)(Bk + 64 + tx * 4);
        float av[8] = {a0.x, a0.y, a0.z, a0.w, a1.x, a1.y, a1.z, a1.w};
        float bv[8] = {b0.x, b0.y, b0.z, b0.w, b1.x, b1.y, b1.z, b1.w};
        #pragma unroll
        for (int i = 0; i < 8; i++)
            #pragma unroll
            for (int j = 0; j < 8; j++)
                acc[i][j] = __fmaf_rn(av[i], bv[j], acc[i][j]);
    }
    __syncthreads();
    u64* rowP = (u64*)sh;
    u64* colP = rowP + TS;
    if (tid < TS) { rowP[tid] = 0ull; colP[tid] = 0ull; }
    __syncthreads();
    #pragma unroll
    for (int i = 0; i < 8; i++) {
        int lr = (i < 4) ? (ty * 4 + i) : (64 + ty * 4 + i - 4);
        u64 best = 0ull;
        #pragma unroll
        for (int j = 0; j < 8; j++) {
            int gc = cb + ((j < 4) ? (tx * 4 + j) : (64 + tx * 4 + j - 4));
            u64 pk = ((u64)fkey(acc[i][j]) << 32) | (u64)(0xFFFFFFFFu - (u32)gc);
            if (pk > best) best = pk;
        }
        atomicMax(&rowP[lr], best);
    }
    #pragma unroll
    for (int j = 0; j < 8; j++) {
        int lc = (j < 4) ? (tx * 4 + j) : (64 + tx * 4 + j - 4);
        u64 best = 0ull;
        #pragma unroll
        for (int i = 0; i < 8; i++) {
            int gr = rb + ((i < 4) ? (ty * 4 + i) : (64 + ty * 4 + i - 4));
            u64 pk = ((u64)fkey(acc[i][j]) << 32) | (u64)(0xFFFFFFFFu - (u32)gr);
            if (pk > best) best = pk;
        }
        atomicMax(&colP[lc], best);
    }
    __syncthreads();
    if (tid < TS) {
        atomicMax(&g_rowP[rb + tid], rowP[tid]);
        atomicMax(&g_colP[cb + tid], colP[tid]);
    }
}

__global__ void k_final(float* __restrict__ dout) {
    int k = blockIdx.x * blockDim.x + threadIdx.x;   // exact: 4096
    u64 rp = g_rowP[k];
    float sc = unfkey((u32)(rp >> 32));
    u32 m01 = 0xFFFFFFFFu - (u32)rp;
    u64 cp = g_colP[m01];
    u32 m10 = 0xFFFFFFFFu - (u32)cp;
    bool valid = (m10 == (u32)k) && (sc > 0.1f);
    dout[OFF_MATCH + k] = (float)m01;
    dout[OFF_SCORE + k] = sc;
    dout[OFF_VALID + k] = valid ? 1.f : 0.f;
}

extern "C" void kernel_launch(void* const* d_in, const int* in_sizes, int n_in,
                              void* d_out, int out_size) {
    const float* feats   = (const float*)d_in[0];
    const float* logits  = (const float*)d_in[1];
    const float* heatmap = (const float*)d_in[2];
    float* out = (float*)d_out;

    cudaFuncSetAttribute(k_sim, cudaFuncAttributeMaxDynamicSharedMemorySize, 64 * TS * 2 * 4);

    k_init<<<256, 256>>>();
    k_shuffle<<<150, 256>>>(logits);
    k_normfeats<<<150, 256>>>(feats);
    k_nms<<<2 * NPIX / 256, 256>>>(heatmap, out);
    k_scan<0><<<2, 256>>>();
    k_sel0<<<2 * NPIX / 256, 256>>>();
    k_scan<1><<<2, 256>>>();
    k_selmid<1><<<dim3(128, 2), 256>>>();
    k_scan<2><<<2, 256>>>();
    k_selmid<2><<<dim3(128, 2), 256>>>();
    k_scan<3><<<2, 256>>>();
    k_sel3<<<dim3(128, 2), 256>>>();
    k_rank<<<dim3(K_TOP / 256, 2), 256>>>(out);
    k_desc<<<dim3(K_TOP, 2), 32>>>();
    k_sim<<<dim3(K_TOP / TS, K_TOP / TS), 256, 64 * TS * 2 * 4>>>();
    k_final<<<K_TOP / 256, 256>>>(out);
}

// round 10
// speedup vs baseline: 1.3773x; 1.3337x over previous
#include <cuda_runtime.h>

typedef unsigned int u32;
typedef unsigned long long u64;

extern "C" __device__ float __nv_expf(float);   // libdevice expf (matches XLA)

#define K_TOP 4096
#define W_IMG 640
#define H_IMG 480
#define NPIX (W_IMG * H_IMG)      // 307200
#define WC 80
#define HC 60
#define NC (WC * HC)              // 4800
#define CH 64
#define CAND_MAX 320000

#define OFF_KPTS  0
#define OFF_MATCH 16384
#define OFF_SCORE 20480
#define OFF_VALID 24576
#define OFF_H     28672
#define OFF_R     643072

__device__ float g_Hs[2 * NPIX];
__device__ float g_FS[2 * NPIX];
__device__ float g_nf[2 * CH * NC];
__device__ u32   g_hist[2][2][65536];
__device__ u64   g_prefix[2];
__device__ u32   g_krem[2];
__device__ u32   g_cnt[2];
__device__ u32   g_candn[2][2];
__device__ u64   g_cand[2][2][CAND_MAX];
__device__ u64   g_sel[2][K_TOP];
__device__ int   g_topidx[2][K_TOP];
__device__ float g_desc[2][K_TOP][CH];
__device__ u64   g_rowP[K_TOP];
__device__ u64   g_colP[K_TOP];

__device__ __forceinline__ u32 fkey(float f) {
    u32 u = __float_as_uint(f);
    return (u >> 31) ? ~u : (u | 0x80000000u);
}
__device__ __forceinline__ float unfkey(u32 k) {
    return __uint_as_float((k >> 31) ? (k & 0x7FFFFFFFu) : ~k);
}

__device__ __forceinline__ u32 warp_append(u32* counter, u32 mask) {
    int lane = threadIdx.x & 31;
    u32 ldr = __ffs(mask) - 1;
    u32 base = 0;
    if ((u32)lane == ldr) base = atomicAdd(counter, __popc(mask));
    base = __shfl_sync(mask, base, ldr);
    return base + __popc(mask & ((1u << lane) - 1));
}

__global__ void k_init() {
    int i = blockIdx.x * blockDim.x + threadIdx.x;
    int st = blockDim.x * gridDim.x;
    u32* h = &g_hist[0][0][0];
    for (int j = i; j < 2 * 2 * 65536; j += st) h[j] = 0;
    for (int j = i; j < K_TOP; j += st) { g_rowP[j] = 0ull; g_colP[j] = 0ull; }
    if (i < 2) {
        g_prefix[i] = 0ull; g_krem[i] = K_TOP; g_cnt[i] = 0;
        g_candn[i][0] = 0; g_candn[i][1] = 0;
    }
}

// fused: blocks 0..149 softmax+shuffle (XLA column-reduce order),
//        blocks 150..299 feats norm (same association). smem-staged coalesced.
__global__ void k_prep(const float* __restrict__ logits,
                       const float* __restrict__ feats) {
    __shared__ float sm[65 * 65 + 65];
    int blk = blockIdx.x;
    int lane = threadIdx.x & 31, wrp = threadIdx.x >> 5;
    if (blk < 150) {
        int b = blk / 75;
        int cellbase = (blk % 75) * 64;
        const float* p = logits + (size_t)b * 65 * NC + cellbase;
        for (int i = threadIdx.x; i < 65 * 64; i += 256) {
            int ch = i >> 6, cl = i & 63;
            sm[ch * 65 + cl] = p[ch * NC + cl];
        }
        __syncthreads();
        float* out = g_Hs + (size_t)b * NPIX;
        #pragma unroll
        for (int s = 0; s < 8; s++) {
            int cell = wrp * 8 + s;
            float x0 = sm[lane * 65 + cell];
            float x1 = sm[(lane + 32) * 65 + cell];
            float x2 = (lane == 0) ? sm[64 * 65 + cell] : __int_as_float(0xff800000);
            float m = fmaxf(fmaxf(x0, x1), x2);
            #pragma unroll
            for (int off = 16; off > 0; off >>= 1)
                m = fmaxf(m, __shfl_xor_sync(0xFFFFFFFFu, m, off));
            float e0 = __nv_expf(__fsub_rn(x0, m));
            float e1 = __nv_expf(__fsub_rn(x1, m));
            float e2 = __nv_expf(__fsub_rn(x2, m));
            float partial = __fadd_rn(__fadd_rn(e0, e1), e2);
            #pragma unroll
            for (int off = 16; off > 0; off >>= 1)
                partial = __fadd_rn(partial, __shfl_down_sync(0xFFFFFFFFu, partial, off));
            float ssum = __shfl_sync(0xFFFFFFFFu, partial, 0);
            int gcell = cellbase + cell;
            int h = gcell / WC, w = gcell % WC;
            int c0 = lane, c1 = lane + 32;
            out[(h * 8 + (c0 >> 3)) * W_IMG + (w * 8 + (c0 & 7))] = __fdiv_rn(e0, ssum);
            out[(h * 8 + (c1 >> 3)) * W_IMG + (w * 8 + (c1 & 7))] = __fdiv_rn(e1, ssum);
        }
    } else {
        int blk2 = blk - 150;
        int b = blk2 / 75;
        int cellbase = (blk2 % 75) * 64;
        float* nrm = sm + 64 * 65;
        const float* f = feats + (size_t)b * CH * NC + cellbase;
        float* o = g_nf + (size_t)b * CH * NC + cellbase;
        for (int i = threadIdx.x; i < 64 * 64; i += 256) {
            int ch = i >> 6, cl = i & 63;
            sm[ch * 65 + cl] = f[ch * NC + cl];
        }
        __syncthreads();
        #pragma unroll
        for (int s = 0; s < 8; s++) {
            int cell = wrp * 8 + s;
            float x0 = sm[lane * 65 + cell];
            float x1 = sm[(lane + 32) * 65 + cell];
            float partial = __fadd_rn(__fmul_rn(x0, x0), __fmul_rn(x1, x1));
            #pragma unroll
            for (int off = 16; off > 0; off >>= 1)
                partial = __fadd_rn(partial, __shfl_down_sync(0xFFFFFFFFu, partial, off));
            if (lane == 0) nrm[cell] = fmaxf(__fsqrt_rn(partial), 1e-12f);
        }
        __syncthreads();
        for (int i = threadIdx.x; i < 64 * 64; i += 256) {
            int ch = i >> 6, cl = i & 63;
            o[ch * NC + cl] = __fdiv_rn(sm[ch * 65 + cl], nrm[cl]);
        }
    }
}

// 5x5 NMS (smem-tiled 320-wide strips) + bilinear reliability + level-0 hist
__global__ void k_nms(const float* __restrict__ heatmap, float* __restrict__ dout) {
    __shared__ float tile[5][324];
    int tid = threadIdx.x;                       // 320 threads
    int gid = blockIdx.x * 320 + tid;            // exact: 2*NPIX (1920 blocks)
    int b = gid / NPIX, p = gid % NPIX;
    int oy = p / W_IMG;
    int xbase = p % W_IMG - tid;                 // 0 or 320 (strip base)
    const float* Hs = g_Hs + (size_t)b * NPIX;
    for (int i = tid; i < 5 * 324; i += 320) {
        int rr = i / 324, cc = i % 324;
        int row = oy - 2 + rr, col = xbase - 2 + cc;
        float v = __int_as_float(0xff800000);
        if ((unsigned)row < H_IMG && (unsigned)col < W_IMG)
            v = Hs[row * W_IMG + col];
        tile[rr][cc] = v;
    }
    __syncthreads();
    int ox = xbase + tid;

    float sy = __fsub_rn(__fmul_rn(__fadd_rn((float)oy, 0.5f), 0.125f), 0.5f);
    float sx = __fsub_rn(__fmul_rn(__fadd_rn((float)ox, 0.5f), 0.125f), 0.5f);
    int iy0 = (int)floorf(sy);
    int ix0 = (int)floorf(sx);
    float fy = __fsub_rn(sy, (float)iy0);
    float fx = __fsub_rn(sx, (float)ix0);
    int y0 = iy0 < 0 ? 0 : iy0;
    int y1 = iy0 >= HC - 1 ? HC - 1 : iy0 + 1;
    int x0 = ix0 < 0 ? 0 : ix0;
    int x1 = ix0 >= WC - 1 ? WC - 1 : ix0 + 1;
    float wy0 = iy0 < 0 ? 0.f : (iy0 >= HC - 1 ? 1.f : __fsub_rn(1.f, fy));
    float wy1 = iy0 < 0 ? 1.f : (iy0 >= HC - 1 ? 0.f : fy);
    float wx0 = ix0 < 0 ? 0.f : (ix0 >= WC - 1 ? 1.f : __fsub_rn(1.f, fx));
    float wx1 = ix0 < 0 ? 1.f : (ix0 >= WC - 1 ? 0.f : fx);
    const float* hm = heatmap + (size_t)b * NC;
    float t0 = __fmaf_rn(wx1, hm[y0 * WC + x1], __fmul_rn(wx0, hm[y0 * WC + x0]));
    float t1 = __fmaf_rn(wx1, hm[y1 * WC + x1], __fmul_rn(wx0, hm[y1 * WC + x0]));
    float rel = __fmaf_rn(wy1, t1, __fmul_rn(wy0, t0));

    float x = tile[2][tid + 2];
    float lm = x;
    #pragma unroll
    for (int dy = 0; dy < 5; dy++)
        #pragma unroll
        for (int dx = 0; dx < 5; dx++)
            lm = fmaxf(lm, tile[dy][tid + dx]);
    float fs = (x == lm) ? __fmul_rn(x, rel) : 0.f;
    if (fs == 0.f) fs = 0.f;   // canonicalize -0
    g_FS[gid] = fs;
    dout[OFF_H + gid] = fs;
    dout[OFF_R + gid] = rel;

    u32 bin = fkey(fs) >> 16;
    u32 peers = __match_any_sync(0xFFFFFFFFu, bin);
    if ((u32)(__ffs(peers) - 1) == (tid & 31u))
        atomicAdd(&g_hist[0][b][bin], __popc(peers));
}

// threshold scan: parallel coarse sums; serial walks run on SMEM only
template <int L>
__global__ void k_scan() {
    int b = blockIdx.x;
    const u32* h = g_hist[L][b];
    __shared__ u32 part[256];
    __shared__ u32 fine[256];
    __shared__ int csel;
    __shared__ u32 accs;
    int t = threadIdx.x;
    u32 s = 0;
    #pragma unroll 8
    for (int i = 0; i < 256; i++) s += h[t * 256 + i];
    part[t] = s;
    __syncthreads();
    if (t == 0) {
        u32 krem = g_krem[b], acc = 0;
        int c = 255;
        for (; c > 0; c--) { if (acc + part[c] >= krem) break; acc += part[c]; }
        csel = c; accs = acc;
    }
    __syncthreads();
    fine[t] = h[csel * 256 + t];
    __syncthreads();
    if (t == 0) {
        u32 krem = g_krem[b], acc = accs;
        int v = 255;
        for (; v > 0; v--) { u32 cv = fine[v]; if (acc + cv >= krem) break; acc += cv; }
        g_krem[b] = krem - acc;
        g_prefix[b] = (g_prefix[b] << 16) | (u64)(u32)(csel * 256 + v);
    }
}

// full pass: definite -> g_sel; threshold-bin -> cand[0] + level-1 hist
__global__ void k_sel0() {
    int gid = blockIdx.x * blockDim.x + threadIdx.x;   // exact: 2*NPIX
    int b = gid / NPIX;
    u32 i = gid % NPIX;
    u64 key = ((u64)fkey(g_FS[gid]) << 32) | (u64)(0xFFFFFFFFu - i);
    u32 v0 = (u32)(g_prefix[b] & 0xFFFFu);
    u32 bin = (u32)(key >> 48);
    bool isDef = bin > v0, isCand = bin == v0;
    u32 md = __ballot_sync(0xFFFFFFFFu, isDef);
    if (isDef) {
        u32 pos = warp_append(&g_cnt[b], md);
        if (pos < K_TOP) g_sel[b][pos] = key;
    }
    u32 mc = __ballot_sync(0xFFFFFFFFu, isCand);
    if (isCand) {
        u32 pos = warp_append(&g_candn[b][0], mc);
        if (pos < CAND_MAX) g_cand[b][0][pos] = key;
        u32 bin2 = (u32)(key >> 32) & 0xFFFFu;
        u32 peers = __match_any_sync(mc, bin2);
        if ((u32)(__ffs(peers) - 1) == (threadIdx.x & 31u))
            atomicAdd(&g_hist[1][b][bin2], __popc(peers));
    }
}

// level 1 over candidates: definite -> g_sel; exact-fkey ties -> cand[1]
__global__ void k_sel1() {
    int b = blockIdx.y;
    u32 N = g_candn[b][0];
    u32 v1 = (u32)(g_prefix[b] & 0xFFFFu);
    u32 total = (N + 255u) & ~255u;
    u32 t0 = blockIdx.x * blockDim.x + threadIdx.x;
    u32 stride = gridDim.x * blockDim.x;
    for (u32 t = t0; t < total; t += stride) {
        bool valid = t < N;
        u64 key = valid ? g_cand[b][0][t] : 0ull;
        u32 bin = (u32)(key >> 32) & 0xFFFFu;
        bool isDef = valid && (bin > v1);
        bool isTie = valid && (bin == v1);
        u32 md = __ballot_sync(0xFFFFFFFFu, isDef);
        if (isDef) {
            u32 pos = warp_append(&g_cnt[b], md);
            if (pos < K_TOP) g_sel[b][pos] = key;
        }
        u32 mt = __ballot_sync(0xFFFFFFFFu, isTie);
        if (isTie) {
            u32 pos = warp_append(&g_candn[b][1], mt);
            if (pos < CAND_MAX) g_cand[b][1][pos] = key;
        }
    }
}

// ties share exact fkey: take krem largest keys (= smallest indices) by rank
__global__ void k_tie() {
    int b = blockIdx.x;
    u32 N = g_candn[b][1];
    u32 need = g_krem[b];
    for (u32 t = threadIdx.x; t < N; t += 256) {
        u64 key = g_cand[b][1][t];
        u32 r = 0;
        for (u32 j = 0; j < N; j++) r += (g_cand[b][1][j] > key);
        if (r < need) {
            u32 pos = atomicAdd(&g_cnt[b], 1);
            if (pos < K_TOP) g_sel[b][pos] = key;
        }
    }
}

// rank-by-counting (keys unique): rank = #{keys greater}; emit kpts + topidx
__global__ void k_rank(float* __restrict__ dout) {
    int b = blockIdx.y;
    int i = blockIdx.x * 256 + threadIdx.x;
    u64 my = g_sel[b][i];
    __shared__ u64 tile[256];
    int r = 0;
    for (int t = 0; t < K_TOP; t += 256) {
        tile[threadIdx.x] = g_sel[b][t + threadIdx.x];
        __syncthreads();
        #pragma unroll 8
        for (int j = 0; j < 256; j++) r += (tile[j] > my);
        __syncthreads();
    }
    u32 idx = 0xFFFFFFFFu - (u32)my;
    g_topidx[b][r] = (int)idx;
    float x = (float)(idx % W_IMG), y = (float)(idx / W_IMG);
    dout[OFF_KPTS + (size_t)b * K_TOP * 2 + r * 2 + 0] = x;
    dout[OFF_KPTS + (size_t)b * K_TOP * 2 + r * 2 + 1] = y;
}

// grid-sample + renorm (row-reduce x2 association) — unchanged
__global__ void k_desc() {
    int k = blockIdx.x, b = blockIdx.y, lane = threadIdx.x;   // 32 threads
    int idx = g_topidx[b][k];
    float xf = (float)(idx % W_IMG), yf = (float)(idx / W_IMG);
    float gx = __fsub_rn(__fmul_rn(__fdiv_rn(xf, 639.f), 2.f), 1.f);
    float gy = __fsub_rn(__fmul_rn(__fdiv_rn(yf, 479.f), 2.f), 1.f);
    float ix = __fmul_rn(__fmul_rn(__fadd_rn(gx, 1.f), 0.5f), 79.f);
    float iy = __fmul_rn(__fmul_rn(__fadd_rn(gy, 1.f), 0.5f), 59.f);
    float ix0f = floorf(ix), iy0f = floorf(iy);
    float wx = __fsub_rn(ix, ix0f), wy = __fsub_rn(iy, iy0f);
    float omx = __fsub_rn(1.f, wx), omy = __fsub_rn(1.f, wy);
    int x0 = min(max((int)ix0f, 0), WC - 1), y0 = min(max((int)iy0f, 0), HC - 1);
    int x1 = min(x0 + 1, WC - 1), y1 = min(y0 + 1, HC - 1);
    int p00 = y0 * WC + x0, p01 = y0 * WC + x1, p10 = y1 * WC + x0, p11 = y1 * WC + x1;
    float v[2];
    #pragma unroll
    for (int t = 0; t < 2; t++) {
        int c = 2 * lane + t;
        const float* f = g_nf + ((size_t)b * CH + c) * NC;
        float t1 = __fmul_rn(__fmul_rn(f[p00], omx), omy);
        float t2 = __fmul_rn(__fmul_rn(f[p01], wx), omy);
        float t3 = __fmul_rn(__fmul_rn(f[p10], omx), wy);
        float t4 = __fmul_rn(__fmul_rn(f[p11], wx), wy);
        v[t] = __fadd_rn(__fadd_rn(__fadd_rn(t1, t2), t3), t4);
    }
    float pr = __fadd_rn(__fmul_rn(v[0], v[0]), __fmul_rn(v[1], v[1]));
    #pragma unroll
    for (int off = 16; off > 0; off >>= 1)
        pr = __fadd_rn(pr, __shfl_down_sync(0xFFFFFFFFu, pr, off));
    float n = fmaxf(__fsqrt_rn(__shfl_sync(0xFFFFFFFFu, pr, 0)), 1e-12f);
    g_desc[b][k][2 * lane + 0] = __fdiv_rn(v[0], n);
    g_desc[b][k][2 * lane + 1] = __fdiv_rn(v[1], n);
}

// sim: VALIDATED fp32 ascending-k FFMA chain; fused row/col argmax. UNCHANGED.
#define TS 128
__global__ void k_sim() {
    extern __shared__ float sh[];
    float* As = sh;             // [64][128] k-major
    float* Bs = sh + 64 * TS;   // [64][128] k-major
    int tid = threadIdx.x;
    int rb = blockIdx.y * TS;
    int cb = blockIdx.x * TS;
    const float4* d0 = (const float4*)&g_desc[0][0][0];
    const float4* d1 = (const float4*)&g_desc[1][0][0];
    for (int t = tid; t < TS * 16; t += 256) {
        int r = t >> 4, c4 = t & 15;
        float4 a = d0[(size_t)(rb + r) * 16 + c4];
        As[(c4 * 4 + 0) * TS + r] = a.x; As[(c4 * 4 + 1) * TS + r] = a.y;
        As[(c4 * 4 + 2) * TS + r] = a.z; As[(c4 * 4 + 3) * TS + r] = a.w;
        float4 bv = d1[(size_t)(cb + r) * 16 + c4];
        Bs[(c4 * 4 + 0) * TS + r] = bv.x; Bs[(c4 * 4 + 1) * TS + r] = bv.y;
        Bs[(c4 * 4 + 2) * TS + r] = bv.z; Bs[(c4 * 4 + 3) * TS + r] = bv.w;
    }
    __syncthreads();
    int tx = tid & 15, ty = tid >> 4;
    float acc[8][8];
    #pragma unroll
    for (int i = 0; i < 8; i++)
        #pragma unroll
        for (int j = 0; j < 8; j++) acc[i][j] = 0.f;
    #pragma unroll 4
    for (int kk = 0; kk < 64; kk++) {     // strictly ascending k
        const float* Ak = As + kk * TS;
        const float* Bk = Bs + kk * TS;
        float4 a0 = *(const float4*)(Ak + ty * 4);
        float4 a1 = *(const float4*)(Ak + 64 + ty * 4);
        float4 b0 = *(const float4*)(Bk + tx * 4);
        float4 b1 = *(const float4*)(Bk + 64 + tx * 4);
        float av[8] = {a0.x, a0.y, a0.z, a0.w, a1.x, a1.y, a1.z, a1.w};
        float bv[8] = {b0.x, b0.y, b0.z, b0.w, b1.x, b1.y, b1.z, b1.w};
        #pragma unroll
        for (int i = 0; i < 8; i++)
            #pragma unroll
            for (int j = 0; j < 8; j++)
                acc[i][j] = __fmaf_rn(av[i], bv[j], acc[i][j]);
    }
    __syncthreads();
    u64* rowP = (u64*)sh;
    u64* colP = rowP + TS;
    if (tid < TS) { rowP[tid] = 0ull; colP[tid] = 0ull; }
    __syncthreads();
    #pragma unroll
    for (int i = 0; i < 8; i++) {
        int lr = (i < 4) ? (ty * 4 + i) : (64 + ty * 4 + i - 4);
        u64 best = 0ull;
        #pragma unroll
        for (int j = 0; j < 8; j++) {
            int gc = cb + ((j < 4) ? (tx * 4 + j) : (64 + tx * 4 + j - 4));
            u64 pk = ((u64)fkey(acc[i][j]) << 32) | (u64)(0xFFFFFFFFu - (u32)gc);
            if (pk > best) best = pk;
        }
        atomicMax(&rowP[lr], best);
    }
    #pragma unroll
    for (int j = 0; j < 8; j++) {
        int lc = (j < 4) ? (tx * 4 + j) : (64 + tx * 4 + j - 4);
        u64 best = 0ull;
        #pragma unroll
        for (int i = 0; i < 8; i++) {
            int gr = rb + ((i < 4) ? (ty * 4 + i) : (64 + ty * 4 + i - 4));
            u64 pk = ((u64)fkey(acc[i][j]) << 32) | (u64)(0xFFFFFFFFu - (u32)gr);
            if (pk > best) best = pk;
        }
        atomicMax(&colP[lc], best);
    }
    __syncthreads();
    if (tid < TS) {
        atomicMax(&g_rowP[rb + tid], rowP[tid]);
        atomicMax(&g_colP[cb + tid], colP[tid]);
    }
}

__global__ void k_final(float* __restrict__ dout) {
    int k = blockIdx.x * blockDim.x + threadIdx.x;   // exact: 4096
    u64 rp = g_rowP[k];
    float sc = unfkey((u32)(rp >> 32));
    u32 m01 = 0xFFFFFFFFu - (u32)rp;
    u64 cp = g_colP[m01];
    u32 m10 = 0xFFFFFFFFu - (u32)cp;
    bool valid = (m10 == (u32)k) && (sc > 0.1f);
    dout[OFF_MATCH + k] = (float)m01;
    dout[OFF_SCORE + k] = sc;
    dout[OFF_VALID + k] = valid ? 1.f : 0.f;
}

extern "C" void kernel_launch(void* const* d_in, const int* in_sizes, int n_in,
                              void* d_out, int out_size) {
    const float* feats   = (const float*)d_in[0];
    const float* logits  = (const float*)d_in[1];
    const float* heatmap = (const float*)d_in[2];
    float* out = (float*)d_out;

    cudaFuncSetAttribute(k_sim, cudaFuncAttributeMaxDynamicSharedMemorySize, 64 * TS * 2 * 4);

    k_init<<<256, 256>>>();
    k_prep<<<300, 256>>>(logits, feats);
    k_nms<<<2 * NPIX / 320, 320>>>(heatmap, out);
    k_scan<0><<<2, 256>>>();
    k_sel0<<<2 * NPIX / 256, 256>>>();
    k_scan<1><<<2, 256>>>();
    k_sel1<<<dim3(64, 2), 256>>>();
    k_tie<<<2, 256>>>();
    k_rank<<<dim3(K_TOP / 256, 2), 256>>>(out);
    k_desc<<<dim3(K_TOP, 2), 32>>>();
    k_sim<<<dim3(K_TOP / TS, K_TOP / TS), 256, 64 * TS * 2 * 4>>>();
    k_final<<<K_TOP / 256, 256>>>(out);
}

// round 11
// speedup vs baseline: 1.6936x; 1.2296x over previous
#include <cuda_runtime.h>

typedef unsigned int u32;
typedef unsigned long long u64;

extern "C" __device__ float __nv_expf(float);   // libdevice expf (matches XLA)

#define K_TOP 4096
#define W_IMG 640
#define H_IMG 480
#define NPIX (W_IMG * H_IMG)      // 307200
#define WC 80
#define HC 60
#define NC (WC * HC)              // 4800
#define CH 64
#define CAND_MAX 320000

#define OFF_KPTS  0
#define OFF_MATCH 16384
#define OFF_SCORE 20480
#define OFF_VALID 24576
#define OFF_H     28672
#define OFF_R     643072

__device__ float g_Hs[2 * NPIX];
__device__ float g_FS[2 * NPIX];
__device__ float g_nf[2 * CH * NC];
__device__ u32   g_hist[2][2][65536];
__device__ u64   g_prefix[2];
__device__ u32   g_krem[2];
__device__ u32   g_cnt[2];
__device__ u32   g_candn[2][2];
__device__ u64   g_cand[2][2][CAND_MAX];
__device__ u64   g_sel[2][K_TOP];
__device__ int   g_topidx[2][K_TOP];
__device__ float g_desc[2][K_TOP][CH];
__device__ u64   g_rowP[K_TOP];
__device__ u64   g_colP[K_TOP];

__device__ __forceinline__ u32 fkey(float f) {
    u32 u = __float_as_uint(f);
    return (u >> 31) ? ~u : (u | 0x80000000u);
}
__device__ __forceinline__ float unfkey(u32 k) {
    return __uint_as_float((k >> 31) ? (k & 0x7FFFFFFFu) : ~k);
}

__device__ __forceinline__ u32 warp_append(u32* counter, u32 mask) {
    int lane = threadIdx.x & 31;
    u32 ldr = __ffs(mask) - 1;
    u32 base = 0;
    if ((u32)lane == ldr) base = atomicAdd(counter, __popc(mask));
    base = __shfl_sync(mask, base, ldr);
    return base + __popc(mask & ((1u << lane) - 1));
}

__global__ void k_init() {
    int i = blockIdx.x * blockDim.x + threadIdx.x;
    int st = blockDim.x * gridDim.x;
    u32* h = &g_hist[0][0][0];
    for (int j = i; j < 2 * 2 * 65536; j += st) h[j] = 0;
    for (int j = i; j < K_TOP; j += st) { g_rowP[j] = 0ull; g_colP[j] = 0ull; }
    if (i < 2) {
        g_prefix[i] = 0ull; g_krem[i] = K_TOP; g_cnt[i] = 0;
        g_candn[i][0] = 0; g_candn[i][1] = 0;
    }
}

// fused: blocks 0..149 softmax+shuffle (XLA column-reduce order),
//        blocks 150..299 feats norm (same association). smem-staged coalesced.
__global__ void k_prep(const float* __restrict__ logits,
                       const float* __restrict__ feats) {
    __shared__ float sm[65 * 65 + 65];
    int blk = blockIdx.x;
    int lane = threadIdx.x & 31, wrp = threadIdx.x >> 5;
    if (blk < 150) {
        int b = blk / 75;
        int cellbase = (blk % 75) * 64;
        const float* p = logits + (size_t)b * 65 * NC + cellbase;
        for (int i = threadIdx.x; i < 65 * 64; i += 256) {
            int ch = i >> 6, cl = i & 63;
            sm[ch * 65 + cl] = p[ch * NC + cl];
        }
        __syncthreads();
        float* out = g_Hs + (size_t)b * NPIX;
        #pragma unroll
        for (int s = 0; s < 8; s++) {
            int cell = wrp * 8 + s;
            float x0 = sm[lane * 65 + cell];
            float x1 = sm[(lane + 32) * 65 + cell];
            float x2 = (lane == 0) ? sm[64 * 65 + cell] : __int_as_float(0xff800000);
            float m = fmaxf(fmaxf(x0, x1), x2);
            #pragma unroll
            for (int off = 16; off > 0; off >>= 1)
                m = fmaxf(m, __shfl_xor_sync(0xFFFFFFFFu, m, off));
            float e0 = __nv_expf(__fsub_rn(x0, m));
            float e1 = __nv_expf(__fsub_rn(x1, m));
            float e2 = __nv_expf(__fsub_rn(x2, m));
            float partial = __fadd_rn(__fadd_rn(e0, e1), e2);
            #pragma unroll
            for (int off = 16; off > 0; off >>= 1)
                partial = __fadd_rn(partial, __shfl_down_sync(0xFFFFFFFFu, partial, off));
            float ssum = __shfl_sync(0xFFFFFFFFu, partial, 0);
            int gcell = cellbase + cell;
            int h = gcell / WC, w = gcell % WC;
            int c0 = lane, c1 = lane + 32;
            out[(h * 8 + (c0 >> 3)) * W_IMG + (w * 8 + (c0 & 7))] = __fdiv_rn(e0, ssum);
            out[(h * 8 + (c1 >> 3)) * W_IMG + (w * 8 + (c1 & 7))] = __fdiv_rn(e1, ssum);
        }
    } else {
        int blk2 = blk - 150;
        int b = blk2 / 75;
        int cellbase = (blk2 % 75) * 64;
        float* nrm = sm + 64 * 65;
        const float* f = feats + (size_t)b * CH * NC + cellbase;
        float* o = g_nf + (size_t)b * CH * NC + cellbase;
        for (int i = threadIdx.x; i < 64 * 64; i += 256) {
            int ch = i >> 6, cl = i & 63;
            sm[ch * 65 + cl] = f[ch * NC + cl];
        }
        __syncthreads();
        #pragma unroll
        for (int s = 0; s < 8; s++) {
            int cell = wrp * 8 + s;
            float x0 = sm[lane * 65 + cell];
            float x1 = sm[(lane + 32) * 65 + cell];
            float partial = __fadd_rn(__fmul_rn(x0, x0), __fmul_rn(x1, x1));
            #pragma unroll
            for (int off = 16; off > 0; off >>= 1)
                partial = __fadd_rn(partial, __shfl_down_sync(0xFFFFFFFFu, partial, off));
            if (lane == 0) nrm[cell] = fmaxf(__fsqrt_rn(partial), 1e-12f);
        }
        __syncthreads();
        for (int i = threadIdx.x; i < 64 * 64; i += 256) {
            int ch = i >> 6, cl = i & 63;
            o[ch * NC + cl] = __fdiv_rn(sm[ch * 65 + cl], nrm[cl]);
        }
    }
}

// 5x5 NMS (smem-tiled 320-wide strips) + bilinear reliability + level-0 hist
__global__ void k_nms(const float* __restrict__ heatmap, float* __restrict__ dout) {
    __shared__ float tile[5][324];
    int tid = threadIdx.x;                       // 320 threads
    int gid = blockIdx.x * 320 + tid;            // exact: 2*NPIX (1920 blocks)
    int b = gid / NPIX, p = gid % NPIX;
    int oy = p / W_IMG;
    int xbase = p % W_IMG - tid;                 // 0 or 320 (strip base)
    const float* Hs = g_Hs + (size_t)b * NPIX;
    for (int i = tid; i < 5 * 324; i += 320) {
        int rr = i / 324, cc = i % 324;
        int row = oy - 2 + rr, col = xbase - 2 + cc;
        float v = __int_as_float(0xff800000);
        if ((unsigned)row < H_IMG && (unsigned)col < W_IMG)
            v = Hs[row * W_IMG + col];
        tile[rr][cc] = v;
    }
    __syncthreads();
    int ox = xbase + tid;

    float sy = __fsub_rn(__fmul_rn(__fadd_rn((float)oy, 0.5f), 0.125f), 0.5f);
    float sx = __fsub_rn(__fmul_rn(__fadd_rn((float)ox, 0.5f), 0.125f), 0.5f);
    int iy0 = (int)floorf(sy);
    int ix0 = (int)floorf(sx);
    float fy = __fsub_rn(sy, (float)iy0);
    float fx = __fsub_rn(sx, (float)ix0);
    int y0 = iy0 < 0 ? 0 : iy0;
    int y1 = iy0 >= HC - 1 ? HC - 1 : iy0 + 1;
    int x0 = ix0 < 0 ? 0 : ix0;
    int x1 = ix0 >= WC - 1 ? WC - 1 : ix0 + 1;
    float wy0 = iy0 < 0 ? 0.f : (iy0 >= HC - 1 ? 1.f : __fsub_rn(1.f, fy));
    float wy1 = iy0 < 0 ? 1.f : (iy0 >= HC - 1 ? 0.f : fy);
    float wx0 = ix0 < 0 ? 0.f : (ix0 >= WC - 1 ? 1.f : __fsub_rn(1.f, fx));
    float wx1 = ix0 < 0 ? 1.f : (ix0 >= WC - 1 ? 0.f : fx);
    const float* hm = heatmap + (size_t)b * NC;
    float t0 = __fmaf_rn(wx1, hm[y0 * WC + x1], __fmul_rn(wx0, hm[y0 * WC + x0]));
    float t1 = __fmaf_rn(wx1, hm[y1 * WC + x1], __fmul_rn(wx0, hm[y1 * WC + x0]));
    float rel = __fmaf_rn(wy1, t1, __fmul_rn(wy0, t0));

    float x = tile[2][tid + 2];
    float lm = x;
    #pragma unroll
    for (int dy = 0; dy < 5; dy++)
        #pragma unroll
        for (int dx = 0; dx < 5; dx++)
            lm = fmaxf(lm, tile[dy][tid + dx]);
    float fs = (x == lm) ? __fmul_rn(x, rel) : 0.f;
    if (fs == 0.f) fs = 0.f;   // canonicalize -0
    g_FS[gid] = fs;
    dout[OFF_H + gid] = fs;
    dout[OFF_R + gid] = rel;

    u32 bin = fkey(fs) >> 16;
    u32 peers = __match_any_sync(0xFFFFFFFFu, bin);
    if ((u32)(__ffs(peers) - 1) == (tid & 31u))
        atomicAdd(&g_hist[0][b][bin], __popc(peers));
}

// threshold scan: 1024 threads, uint4 coarse sums (high MLP), smem serial walks
template <int L>
__global__ void k_scan() {
    int b = blockIdx.x;
    const uint4* h4 = (const uint4*)g_hist[L][b];
    __shared__ u32 sm1[1024];
    __shared__ u32 part[256];
    __shared__ u32 fine[256];
    __shared__ int csel;
    __shared__ u32 accs;
    int t = threadIdx.x;
    u32 s = 0;
    #pragma unroll
    for (int i = 0; i < 16; i++) {       // entries [t*64, t*64+64)
        uint4 v = h4[t * 16 + i];
        s += v.x + v.y + v.z + v.w;
    }
    sm1[t] = s;
    __syncthreads();
    if (t < 256)
        part[t] = sm1[4 * t] + sm1[4 * t + 1] + sm1[4 * t + 2] + sm1[4 * t + 3];
    __syncthreads();
    if (t == 0) {
        u32 krem = g_krem[b], acc = 0;
        int c = 255;
        for (; c > 0; c--) { if (acc + part[c] >= krem) break; acc += part[c]; }
        csel = c; accs = acc;
    }
    __syncthreads();
    if (t < 256) fine[t] = g_hist[L][b][csel * 256 + t];
    __syncthreads();
    if (t == 0) {
        u32 krem = g_krem[b], acc = accs;
        int v = 255;
        for (; v > 0; v--) { u32 cv = fine[v]; if (acc + cv >= krem) break; acc += cv; }
        g_krem[b] = krem - acc;
        g_prefix[b] = (g_prefix[b] << 16) | (u64)(u32)(csel * 256 + v);
    }
}

// full pass: definite -> g_sel; threshold-bin -> cand[0] + level-1 hist
__global__ void k_sel0() {
    int gid = blockIdx.x * blockDim.x + threadIdx.x;   // exact: 2*NPIX
    int b = gid / NPIX;
    u32 i = gid % NPIX;
    u64 key = ((u64)fkey(g_FS[gid]) << 32) | (u64)(0xFFFFFFFFu - i);
    u32 v0 = (u32)(g_prefix[b] & 0xFFFFu);
    u32 bin = (u32)(key >> 48);
    bool isDef = bin > v0, isCand = bin == v0;
    u32 md = __ballot_sync(0xFFFFFFFFu, isDef);
    if (isDef) {
        u32 pos = warp_append(&g_cnt[b], md);
        if (pos < K_TOP) g_sel[b][pos] = key;
    }
    u32 mc = __ballot_sync(0xFFFFFFFFu, isCand);
    if (isCand) {
        u32 pos = warp_append(&g_candn[b][0], mc);
        if (pos < CAND_MAX) g_cand[b][0][pos] = key;
        u32 bin2 = (u32)(key >> 32) & 0xFFFFu;
        u32 peers = __match_any_sync(mc, bin2);
        if ((u32)(__ffs(peers) - 1) == (threadIdx.x & 31u))
            atomicAdd(&g_hist[1][b][bin2], __popc(peers));
    }
}

// level 1 over candidates: definite -> g_sel; exact-fkey ties -> cand[1]
__global__ void k_sel1() {
    int b = blockIdx.y;
    u32 N = g_candn[b][0];
    u32 v1 = (u32)(g_prefix[b] & 0xFFFFu);
    u32 total = (N + 255u) & ~255u;
    u32 t0 = blockIdx.x * blockDim.x + threadIdx.x;
    u32 stride = gridDim.x * blockDim.x;
    for (u32 t = t0; t < total; t += stride) {
        bool valid = t < N;
        u64 key = valid ? g_cand[b][0][t] : 0ull;
        u32 bin = (u32)(key >> 32) & 0xFFFFu;
        bool isDef = valid && (bin > v1);
        bool isTie = valid && (bin == v1);
        u32 md = __ballot_sync(0xFFFFFFFFu, isDef);
        if (isDef) {
            u32 pos = warp_append(&g_cnt[b], md);
            if (pos < K_TOP) g_sel[b][pos] = key;
        }
        u32 mt = __ballot_sync(0xFFFFFFFFu, isTie);
        if (isTie) {
            u32 pos = warp_append(&g_candn[b][1], mt);
            if (pos < CAND_MAX) g_cand[b][1][pos] = key;
        }
    }
}

// ties share exact fkey: take krem largest keys (= smallest indices) by rank
__global__ void k_tie() {
    int b = blockIdx.x;
    u32 N = g_candn[b][1];
    u32 need = g_krem[b];
    for (u32 t = threadIdx.x; t < N; t += 256) {
        u64 key = g_cand[b][1][t];
        u32 r = 0;
        for (u32 j = 0; j < N; j++) r += (g_cand[b][1][j] > key);
        if (r < need) {
            u32 pos = atomicAdd(&g_cnt[b], 1);
            if (pos < K_TOP) g_sel[b][pos] = key;
        }
    }
}

// rank-by-counting (keys unique): rank = #{keys greater}; emit kpts + topidx
__global__ void k_rank(float* __restrict__ dout) {
    int b = blockIdx.y;
    int i = blockIdx.x * 256 + threadIdx.x;
    u64 my = g_sel[b][i];
    __shared__ u64 tile[256];
    int r = 0;
    for (int t = 0; t < K_TOP; t += 256) {
        tile[threadIdx.x] = g_sel[b][t + threadIdx.x];
        __syncthreads();
        #pragma unroll 8
        for (int j = 0; j < 256; j++) r += (tile[j] > my);
        __syncthreads();
    }
    u32 idx = 0xFFFFFFFFu - (u32)my;
    g_topidx[b][r] = (int)idx;
    float x = (float)(idx % W_IMG), y = (float)(idx / W_IMG);
    dout[OFF_KPTS + (size_t)b * K_TOP * 2 + r * 2 + 0] = x;
    dout[OFF_KPTS + (size_t)b * K_TOP * 2 + r * 2 + 1] = y;
}

// grid-sample + renorm (row-reduce x2 association) — unchanged
__global__ void k_desc() {
    int k = blockIdx.x, b = blockIdx.y, lane = threadIdx.x;   // 32 threads
    int idx = g_topidx[b][k];
    float xf = (float)(idx % W_IMG), yf = (float)(idx / W_IMG);
    float gx = __fsub_rn(__fmul_rn(__fdiv_rn(xf, 639.f), 2.f), 1.f);
    float gy = __fsub_rn(__fmul_rn(__fdiv_rn(yf, 479.f), 2.f), 1.f);
    float ix = __fmul_rn(__fmul_rn(__fadd_rn(gx, 1.f), 0.5f), 79.f);
    float iy = __fmul_rn(__fmul_rn(__fadd_rn(gy, 1.f), 0.5f), 59.f);
    float ix0f = floorf(ix), iy0f = floorf(iy);
    float wx = __fsub_rn(ix, ix0f), wy = __fsub_rn(iy, iy0f);
    float omx = __fsub_rn(1.f, wx), omy = __fsub_rn(1.f, wy);
    int x0 = min(max((int)ix0f, 0), WC - 1), y0 = min(max((int)iy0f, 0), HC - 1);
    int x1 = min(x0 + 1, WC - 1), y1 = min(y0 + 1, HC - 1);
    int p00 = y0 * WC + x0, p01 = y0 * WC + x1, p10 = y1 * WC + x0, p11 = y1 * WC + x1;
    float v[2];
    #pragma unroll
    for (int t = 0; t < 2; t++) {
        int c = 2 * lane + t;
        const float* f = g_nf + ((size_t)b * CH + c) * NC;
        float t1 = __fmul_rn(__fmul_rn(f[p00], omx), omy);
        float t2 = __fmul_rn(__fmul_rn(f[p01], wx), omy);
        float t3 = __fmul_rn(__fmul_rn(f[p10], omx), wy);
        float t4 = __fmul_rn(__fmul_rn(f[p11], wx), wy);
        v[t] = __fadd_rn(__fadd_rn(__fadd_rn(t1, t2), t3), t4);
    }
    float pr = __fadd_rn(__fmul_rn(v[0], v[0]), __fmul_rn(v[1], v[1]));
    #pragma unroll
    for (int off = 16; off > 0; off >>= 1)
        pr = __fadd_rn(pr, __shfl_down_sync(0xFFFFFFFFu, pr, off));
    float n = fmaxf(__fsqrt_rn(__shfl_sync(0xFFFFFFFFu, pr, 0)), 1e-12f);
    g_desc[b][k][2 * lane + 0] = __fdiv_rn(v[0], n);
    g_desc[b][k][2 * lane + 1] = __fdiv_rn(v[1], n);
}

// sim: VALIDATED fp32 ascending-k FFMA chain; fused row/col argmax. UNCHANGED.
#define TS 128
__global__ void k_sim() {
    extern __shared__ float sh[];
    float* As = sh;             // [64][128] k-major
    float* Bs = sh + 64 * TS;   // [64][128] k-major
    int tid = threadIdx.x;
    int rb = blockIdx.y * TS;
    int cb = blockIdx.x * TS;
    const float4* d0 = (const float4*)&g_desc[0][0][0];
    const float4* d1 = (const float4*)&g_desc[1][0][0];
    for (int t = tid; t < TS * 16; t += 256) {
        int r = t >> 4, c4 = t & 15;
        float4 a = d0[(size_t)(rb + r) * 16 + c4];
        As[(c4 * 4 + 0) * TS + r] = a.x; As[(c4 * 4 + 1) * TS + r] = a.y;
        As[(c4 * 4 + 2) * TS + r] = a.z; As[(c4 * 4 + 3) * TS + r] = a.w;
        float4 bv = d1[(size_t)(cb + r) * 16 + c4];
        Bs[(c4 * 4 + 0) * TS + r] = bv.x; Bs[(c4 * 4 + 1) * TS + r] = bv.y;
        Bs[(c4 * 4 + 2) * TS + r] = bv.z; Bs[(c4 * 4 + 3) * TS + r] = bv.w;
    }
    __syncthreads();
    int tx = tid & 15, ty = tid >> 4;
    float acc[8][8];
    #pragma unroll
    for (int i = 0; i < 8; i++)
        #pragma unroll
        for (int j = 0; j < 8; j++) acc[i][j] = 0.f;
    #pragma unroll 4
    for (int kk = 0; kk < 64; kk++) {     // strictly ascending k
        const float* Ak = As + kk * TS;
        const float* Bk = Bs + kk * TS;
        float4 a0 = *(const float4*)(Ak + ty * 4);
        float4 a1 = *(const float4*)(Ak + 64 + ty * 4);
        float4 b0 = *(const float4*)(Bk + tx * 4);
        float4 b1 = *(const float4*)(Bk + 64 + tx * 4);
        float av[8] = {a0.x, a0.y, a0.z, a0.w, a1.x, a1.y, a1.z, a1.w};
        float bv[8] = {b0.x, b0.y, b0.z, b0.w, b1.x, b1.y, b1.z, b1.w};
        #pragma unroll
        for (int i = 0; i < 8; i++)
            #pragma unroll
            for (int j = 0; j < 8; j++)
                acc[i][j] = __fmaf_rn(av[i], bv[j], acc[i][j]);
    }
    __syncthreads();
    u64* rowP = (u64*)sh;
    u64* colP = rowP + TS;
    if (tid < TS) { rowP[tid] = 0ull; colP[tid] = 0ull; }
    __syncthreads();
    #pragma unroll
    for (int i = 0; i < 8; i++) {
        int lr = (i < 4) ? (ty * 4 + i) : (64 + ty * 4 + i - 4);
        u64 best = 0ull;
        #pragma unroll
        for (int j = 0; j < 8; j++) {
            int gc = cb + ((j < 4) ? (tx * 4 + j) : (64 + tx * 4 + j - 4));
            u64 pk = ((u64)fkey(acc[i][j]) << 32) | (u64)(0xFFFFFFFFu - (u32)gc);
            if (pk > best) best = pk;
        }
        atomicMax(&rowP[lr], best);
    }
    #pragma unroll
    for (int j = 0; j < 8; j++) {
        int lc = (j < 4) ? (tx * 4 + j) : (64 + tx * 4 + j - 4);
        u64 best = 0ull;
        #pragma unroll
        for (int i = 0; i < 8; i++) {
            int gr = rb + ((i < 4) ? (ty * 4 + i) : (64 + ty * 4 + i - 4));
            u64 pk = ((u64)fkey(acc[i][j]) << 32) | (u64)(0xFFFFFFFFu - (u32)gr);
            if (pk > best) best = pk;
        }
        atomicMax(&colP[lc], best);
    }
    __syncthreads();
    if (tid < TS) {
        atomicMax(&g_rowP[rb + tid], rowP[tid]);
        atomicMax(&g_colP[cb + tid], colP[tid]);
    }
}

__global__ void k_final(float* __restrict__ dout) {
    int k = blockIdx.x * blockDim.x + threadIdx.x;   // exact: 4096
    u64 rp = g_rowP[k];
    float sc = unfkey((u32)(rp >> 32));
    u32 m01 = 0xFFFFFFFFu - (u32)rp;
    u64 cp = g_colP[m01];
    u32 m10 = 0xFFFFFFFFu - (u32)cp;
    bool valid = (m10 == (u32)k) && (sc > 0.1f);
    dout[OFF_MATCH + k] = (float)m01;
    dout[OFF_SCORE + k] = sc;
    dout[OFF_VALID + k] = valid ? 1.f : 0.f;
}

extern "C" void kernel_launch(void* const* d_in, const int* in_sizes, int n_in,
                              void* d_out, int out_size) {
    const float* feats   = (const float*)d_in[0];
    const float* logits  = (const float*)d_in[1];
    const float* heatmap = (const float*)d_in[2];
    float* out = (float*)d_out;

    cudaFuncSetAttribute(k_sim, cudaFuncAttributeMaxDynamicSharedMemorySize, 64 * TS * 2 * 4);

    k_init<<<256, 256>>>();
    k_prep<<<300, 256>>>(logits, feats);
    k_nms<<<2 * NPIX / 320, 320>>>(heatmap, out);
    k_scan<0><<<2, 1024>>>();
    k_sel0<<<2 * NPIX / 256, 256>>>();
    k_scan<1><<<2, 1024>>>();
    k_sel1<<<dim3(64, 2), 256>>>();
    k_tie<<<2, 256>>>();
    k_rank<<<dim3(K_TOP / 256, 2), 256>>>(out);
    k_desc<<<dim3(K_TOP, 2), 32>>>();
    k_sim<<<dim3(K_TOP / TS, K_TOP / TS), 256, 64 * TS * 2 * 4>>>();
    k_final<<<K_TOP / 256, 256>>>(out);
}

// round 12
// speedup vs baseline: 1.8214x; 1.0754x over previous
#include <cuda_runtime.h>

typedef unsigned int u32;
typedef unsigned long long u64;

extern "C" __device__ float __nv_expf(float);   // libdevice expf (matches XLA)

#define K_TOP 4096
#define W_IMG 640
#define H_IMG 480
#define NPIX (W_IMG * H_IMG)      // 307200
#define WC 80
#define HC 60
#define NC (WC * HC)              // 4800
#define CH 64
#define CAND_MAX 320000

#define OFF_KPTS  0
#define OFF_MATCH 16384
#define OFF_SCORE 20480
#define OFF_VALID 24576
#define OFF_H     28672
#define OFF_R     643072

__device__ float g_Hs[2 * NPIX];
__device__ float g_FS[2 * NPIX];
__device__ float g_nf[2 * CH * NC];
__device__ u32   g_hist[2][2][65536];
__device__ u32   g_coarse[2][2][256];
__device__ u64   g_prefix[2];
__device__ u32   g_krem[2];
__device__ u32   g_cnt[2];
__device__ u32   g_candn[2][2];
__device__ u64   g_cand[2][2][CAND_MAX];
__device__ u64   g_sel[2][K_TOP];
__device__ int   g_topidx[2][K_TOP];
__device__ float g_desc[2][K_TOP][CH];
__device__ u64   g_rowP[K_TOP];
__device__ u64   g_colP[K_TOP];

__device__ __forceinline__ u32 fkey(float f) {
    u32 u = __float_as_uint(f);
    return (u >> 31) ? ~u : (u | 0x80000000u);
}
__device__ __forceinline__ float unfkey(u32 k) {
    return __uint_as_float((k >> 31) ? (k & 0x7FFFFFFFu) : ~k);
}

__device__ __forceinline__ u32 warp_append(u32* counter, u32 mask) {
    int lane = threadIdx.x & 31;
    u32 ldr = __ffs(mask) - 1;
    u32 base = 0;
    if ((u32)lane == ldr) base = atomicAdd(counter, __popc(mask));
    base = __shfl_sync(mask, base, ldr);
    return base + __popc(mask & ((1u << lane) - 1));
}

// aggregated histogram add for fine+coarse (mask = active lanes)
__device__ __forceinline__ void hist_add(u32* fine, u32* coarse, u32 bin, u32 mask) {
    u32 peers = __match_any_sync(mask, bin);
    if ((u32)(__ffs(peers) - 1) == (threadIdx.x & 31u))
        atomicAdd(&fine[bin], __popc(peers));
    u32 cbin = bin >> 8;
    u32 cpeers = __match_any_sync(mask, cbin);
    if ((u32)(__ffs(cpeers) - 1) == (threadIdx.x & 31u))
        atomicAdd(&coarse[cbin], __popc(cpeers));
}

__global__ void k_init() {
    int i = blockIdx.x * blockDim.x + threadIdx.x;
    int st = blockDim.x * gridDim.x;
    u32* h = &g_hist[0][0][0];
    for (int j = i; j < 2 * 2 * 65536; j += st) h[j] = 0;
    u32* c = &g_coarse[0][0][0];
    for (int j = i; j < 2 * 2 * 256; j += st) c[j] = 0;
    for (int j = i; j < K_TOP; j += st) { g_rowP[j] = 0ull; g_colP[j] = 0ull; }
    if (i < 2) {
        g_prefix[i] = 0ull; g_krem[i] = K_TOP; g_cnt[i] = 0;
        g_candn[i][0] = 0; g_candn[i][1] = 0;
    }
}

// fused: blocks 0..149 softmax+shuffle (XLA column-reduce order),
//        blocks 150..299 feats norm (same association). smem-staged coalesced.
__global__ void k_prep(const float* __restrict__ logits,
                       const float* __restrict__ feats) {
    __shared__ float sm[65 * 65 + 65];
    int blk = blockIdx.x;
    int lane = threadIdx.x & 31, wrp = threadIdx.x >> 5;
    if (blk < 150) {
        int b = blk / 75;
        int cellbase = (blk % 75) * 64;
        const float* p = logits + (size_t)b * 65 * NC + cellbase;
        for (int i = threadIdx.x; i < 65 * 64; i += 256) {
            int ch = i >> 6, cl = i & 63;
            sm[ch * 65 + cl] = p[ch * NC + cl];
        }
        __syncthreads();
        float* out = g_Hs + (size_t)b * NPIX;
        #pragma unroll
        for (int s = 0; s < 8; s++) {
            int cell = wrp * 8 + s;
            float x0 = sm[lane * 65 + cell];
            float x1 = sm[(lane + 32) * 65 + cell];
            float x2 = (lane == 0) ? sm[64 * 65 + cell] : __int_as_float(0xff800000);
            float m = fmaxf(fmaxf(x0, x1), x2);
            #pragma unroll
            for (int off = 16; off > 0; off >>= 1)
                m = fmaxf(m, __shfl_xor_sync(0xFFFFFFFFu, m, off));
            float e0 = __nv_expf(__fsub_rn(x0, m));
            float e1 = __nv_expf(__fsub_rn(x1, m));
            float e2 = __nv_expf(__fsub_rn(x2, m));
            float partial = __fadd_rn(__fadd_rn(e0, e1), e2);
            #pragma unroll
            for (int off = 16; off > 0; off >>= 1)
                partial = __fadd_rn(partial, __shfl_down_sync(0xFFFFFFFFu, partial, off));
            float ssum = __shfl_sync(0xFFFFFFFFu, partial, 0);
            int gcell = cellbase + cell;
            int h = gcell / WC, w = gcell % WC;
            int c0 = lane, c1 = lane + 32;
            out[(h * 8 + (c0 >> 3)) * W_IMG + (w * 8 + (c0 & 7))] = __fdiv_rn(e0, ssum);
            out[(h * 8 + (c1 >> 3)) * W_IMG + (w * 8 + (c1 & 7))] = __fdiv_rn(e1, ssum);
        }
    } else {
        int blk2 = blk - 150;
        int b = blk2 / 75;
        int cellbase = (blk2 % 75) * 64;
        float* nrm = sm + 64 * 65;
        const float* f = feats + (size_t)b * CH * NC + cellbase;
        float* o = g_nf + (size_t)b * CH * NC + cellbase;
        for (int i = threadIdx.x; i < 64 * 64; i += 256) {
            int ch = i >> 6, cl = i & 63;
            sm[ch * 65 + cl] = f[ch * NC + cl];
        }
        __syncthreads();
        #pragma unroll
        for (int s = 0; s < 8; s++) {
            int cell = wrp * 8 + s;
            float x0 = sm[lane * 65 + cell];
            float x1 = sm[(lane + 32) * 65 + cell];
            float partial = __fadd_rn(__fmul_rn(x0, x0), __fmul_rn(x1, x1));
            #pragma unroll
            for (int off = 16; off > 0; off >>= 1)
                partial = __fadd_rn(partial, __shfl_down_sync(0xFFFFFFFFu, partial, off));
            if (lane == 0) nrm[cell] = fmaxf(__fsqrt_rn(partial), 1e-12f);
        }
        __syncthreads();
        for (int i = threadIdx.x; i < 64 * 64; i += 256) {
            int ch = i >> 6, cl = i & 63;
            o[ch * NC + cl] = __fdiv_rn(sm[ch * 65 + cl], nrm[cl]);
        }
    }
}

// 5x5 NMS (smem-tiled) + bilinear reliability + level-0 fine+coarse hist
__global__ void k_nms(const float* __restrict__ heatmap, float* __restrict__ dout) {
    __shared__ float tile[5][324];
    int tid = threadIdx.x;                       // 320 threads
    int gid = blockIdx.x * 320 + tid;            // exact: 2*NPIX (1920 blocks)
    int b = gid / NPIX, p = gid % NPIX;
    int oy = p / W_IMG;
    int xbase = p % W_IMG - tid;                 // 0 or 320 (strip base)
    const float* Hs = g_Hs + (size_t)b * NPIX;
    for (int i = tid; i < 5 * 324; i += 320) {
        int rr = i / 324, cc = i % 324;
        int row = oy - 2 + rr, col = xbase - 2 + cc;
        float v = __int_as_float(0xff800000);
        if ((unsigned)row < H_IMG && (unsigned)col < W_IMG)
            v = Hs[row * W_IMG + col];
        tile[rr][cc] = v;
    }
    __syncthreads();
    int ox = xbase + tid;

    float sy = __fsub_rn(__fmul_rn(__fadd_rn((float)oy, 0.5f), 0.125f), 0.5f);
    float sx = __fsub_rn(__fmul_rn(__fadd_rn((float)ox, 0.5f), 0.125f), 0.5f);
    int iy0 = (int)floorf(sy);
    int ix0 = (int)floorf(sx);
    float fy = __fsub_rn(sy, (float)iy0);
    float fx = __fsub_rn(sx, (float)ix0);
    int y0 = iy0 < 0 ? 0 : iy0;
    int y1 = iy0 >= HC - 1 ? HC - 1 : iy0 + 1;
    int x0 = ix0 < 0 ? 0 : ix0;
    int x1 = ix0 >= WC - 1 ? WC - 1 : ix0 + 1;
    float wy0 = iy0 < 0 ? 0.f : (iy0 >= HC - 1 ? 1.f : __fsub_rn(1.f, fy));
    float wy1 = iy0 < 0 ? 1.f : (iy0 >= HC - 1 ? 0.f : fy);
    float wx0 = ix0 < 0 ? 0.f : (ix0 >= WC - 1 ? 1.f : __fsub_rn(1.f, fx));
    float wx1 = ix0 < 0 ? 1.f : (ix0 >= WC - 1 ? 0.f : fx);
    const float* hm = heatmap + (size_t)b * NC;
    float t0 = __fmaf_rn(wx1, hm[y0 * WC + x1], __fmul_rn(wx0, hm[y0 * WC + x0]));
    float t1 = __fmaf_rn(wx1, hm[y1 * WC + x1], __fmul_rn(wx0, hm[y1 * WC + x0]));
    float rel = __fmaf_rn(wy1, t1, __fmul_rn(wy0, t0));

    float x = tile[2][tid + 2];
    float lm = x;
    #pragma unroll
    for (int dy = 0; dy < 5; dy++)
        #pragma unroll
        for (int dx = 0; dx < 5; dx++)
            lm = fmaxf(lm, tile[dy][tid + dx]);
    float fs = (x == lm) ? __fmul_rn(x, rel) : 0.f;
    if (fs == 0.f) fs = 0.f;   // canonicalize -0
    g_FS[gid] = fs;
    dout[OFF_H + gid] = fs;
    dout[OFF_R + gid] = rel;

    u32 bin = fkey(fs) >> 16;
    hist_add(g_hist[0][b], g_coarse[0][b], bin, 0xFFFFFFFFu);
}

// threshold scan: coarse counters maintained upstream -> 2KB total reads
template <int L>
__global__ void k_scan() {
    int b = blockIdx.x;
    __shared__ u32 part[256];
    __shared__ u32 fine[256];
    __shared__ int csel;
    __shared__ u32 accs;
    int t = threadIdx.x;
    part[t] = g_coarse[L][b][t];
    __syncthreads();
    if (t == 0) {
        u32 krem = g_krem[b], acc = 0;
        int c = 255;
        for (; c > 0; c--) { if (acc + part[c] >= krem) break; acc += part[c]; }
        csel = c; accs = acc;
    }
    __syncthreads();
    fine[t] = g_hist[L][b][csel * 256 + t];
    __syncthreads();
    if (t == 0) {
        u32 krem = g_krem[b], acc = accs;
        int v = 255;
        for (; v > 0; v--) { u32 cv = fine[v]; if (acc + cv >= krem) break; acc += cv; }
        g_krem[b] = krem - acc;
        g_prefix[b] = (g_prefix[b] << 16) | (u64)(u32)(csel * 256 + v);
    }
}

// full pass: definite -> g_sel; threshold-bin -> cand[0] + level-1 fine+coarse
__global__ void k_sel0() {
    int gid = blockIdx.x * blockDim.x + threadIdx.x;   // exact: 2*NPIX
    int b = gid / NPIX;
    u32 i = gid % NPIX;
    u64 key = ((u64)fkey(g_FS[gid]) << 32) | (u64)(0xFFFFFFFFu - i);
    u32 v0 = (u32)(g_prefix[b] & 0xFFFFu);
    u32 bin = (u32)(key >> 48);
    bool isDef = bin > v0, isCand = bin == v0;
    u32 md = __ballot_sync(0xFFFFFFFFu, isDef);
    if (isDef) {
        u32 pos = warp_append(&g_cnt[b], md);
        if (pos < K_TOP) g_sel[b][pos] = key;
    }
    u32 mc = __ballot_sync(0xFFFFFFFFu, isCand);
    if (isCand) {
        u32 pos = warp_append(&g_candn[b][0], mc);
        if (pos < CAND_MAX) g_cand[b][0][pos] = key;
        u32 bin2 = (u32)(key >> 32) & 0xFFFFu;
        hist_add(g_hist[1][b], g_coarse[1][b], bin2, mc);
    }
}

// level 1 over candidates: definite -> g_sel; exact-fkey ties -> cand[1]
__global__ void k_sel1() {
    int b = blockIdx.y;
    u32 N = g_candn[b][0];
    u32 v1 = (u32)(g_prefix[b] & 0xFFFFu);
    u32 total = (N + 255u) & ~255u;
    u32 t0 = blockIdx.x * blockDim.x + threadIdx.x;
    u32 stride = gridDim.x * blockDim.x;
    for (u32 t = t0; t < total; t += stride) {
        bool valid = t < N;
        u64 key = valid ? g_cand[b][0][t] : 0ull;
        u32 bin = (u32)(key >> 32) & 0xFFFFu;
        bool isDef = valid && (bin > v1);
        bool isTie = valid && (bin == v1);
        u32 md = __ballot_sync(0xFFFFFFFFu, isDef);
        if (isDef) {
            u32 pos = warp_append(&g_cnt[b], md);
            if (pos < K_TOP) g_sel[b][pos] = key;
        }
        u32 mt = __ballot_sync(0xFFFFFFFFu, isTie);
        if (isTie) {
            u32 pos = warp_append(&g_candn[b][1], mt);
            if (pos < CAND_MAX) g_cand[b][1][pos] = key;
        }
    }
}

// ties share exact fkey: take krem largest keys (= smallest indices) by rank
__global__ void k_tie() {
    int b = blockIdx.x;
    u32 N = g_candn[b][1];
    u32 need = g_krem[b];
    for (u32 t = threadIdx.x; t < N; t += 256) {
        u64 key = g_cand[b][1][t];
        u32 r = 0;
        for (u32 j = 0; j < N; j++) r += (g_cand[b][1][j] > key);
        if (r < need) {
            u32 pos = atomicAdd(&g_cnt[b], 1);
            if (pos < K_TOP) g_sel[b][pos] = key;
        }
    }
}

// rank-by-counting (keys unique): rank = #{keys greater}; emit kpts + topidx
__global__ void k_rank(float* __restrict__ dout) {
    int b = blockIdx.y;
    int i = blockIdx.x * 256 + threadIdx.x;
    u64 my = g_sel[b][i];
    __shared__ u64 tile[256];
    int r = 0;
    for (int t = 0; t < K_TOP; t += 256) {
        tile[threadIdx.x] = g_sel[b][t + threadIdx.x];
        __syncthreads();
        #pragma unroll 8
        for (int j = 0; j < 256; j++) r += (tile[j] > my);
        __syncthreads();
    }
    u32 idx = 0xFFFFFFFFu - (u32)my;
    g_topidx[b][r] = (int)idx;
    float x = (float)(idx % W_IMG), y = (float)(idx / W_IMG);
    dout[OFF_KPTS + (size_t)b * K_TOP * 2 + r * 2 + 0] = x;
    dout[OFF_KPTS + (size_t)b * K_TOP * 2 + r * 2 + 1] = y;
}

// grid-sample + renorm (row-reduce x2 association) — unchanged
__global__ void k_desc() {
    int k = blockIdx.x, b = blockIdx.y, lane = threadIdx.x;   // 32 threads
    int idx = g_topidx[b][k];
    float xf = (float)(idx % W_IMG), yf = (float)(idx / W_IMG);
    float gx = __fsub_rn(__fmul_rn(__fdiv_rn(xf, 639.f), 2.f), 1.f);
    float gy = __fsub_rn(__fmul_rn(__fdiv_rn(yf, 479.f), 2.f), 1.f);
    float ix = __fmul_rn(__fmul_rn(__fadd_rn(gx, 1.f), 0.5f), 79.f);
    float iy = __fmul_rn(__fmul_rn(__fadd_rn(gy, 1.f), 0.5f), 59.f);
    float ix0f = floorf(ix), iy0f = floorf(iy);
    float wx = __fsub_rn(ix, ix0f), wy = __fsub_rn(iy, iy0f);
    float omx = __fsub_rn(1.f, wx), omy = __fsub_rn(1.f, wy);
    int x0 = min(max((int)ix0f, 0), WC - 1), y0 = min(max((int)iy0f, 0), HC - 1);
    int x1 = min(x0 + 1, WC - 1), y1 = min(y0 + 1, HC - 1);
    int p00 = y0 * WC + x0, p01 = y0 * WC + x1, p10 = y1 * WC + x0, p11 = y1 * WC + x1;
    float v[2];
    #pragma unroll
    for (int t = 0; t < 2; t++) {
        int c = 2 * lane + t;
        const float* f = g_nf + ((size_t)b * CH + c) * NC;
        float t1 = __fmul_rn(__fmul_rn(f[p00], omx), omy);
        float t2 = __fmul_rn(__fmul_rn(f[p01], wx), omy);
        float t3 = __fmul_rn(__fmul_rn(f[p10], omx), wy);
        float t4 = __fmul_rn(__fmul_rn(f[p11], wx), wy);
        v[t] = __fadd_rn(__fadd_rn(__fadd_rn(t1, t2), t3), t4);
    }
    float pr = __fadd_rn(__fmul_rn(v[0], v[0]), __fmul_rn(v[1], v[1]));
    #pragma unroll
    for (int off = 16; off > 0; off >>= 1)
        pr = __fadd_rn(pr, __shfl_down_sync(0xFFFFFFFFu, pr, off));
    float n = fmaxf(__fsqrt_rn(__shfl_sync(0xFFFFFFFFu, pr, 0)), 1e-12f);
    g_desc[b][k][2 * lane + 0] = __fdiv_rn(v[0], n);
    g_desc[b][k][2 * lane + 1] = __fdiv_rn(v[1], n);
}

// sim: VALIDATED fp32 ascending-k FFMA chain; fused row/col argmax. UNCHANGED.
#define TS 128
__global__ void k_sim() {
    extern __shared__ float sh[];
    float* As = sh;             // [64][128] k-major
    float* Bs = sh + 64 * TS;   // [64][128] k-major
    int tid = threadIdx.x;
    int rb = blockIdx.y * TS;
    int cb = blockIdx.x * TS;
    const float4* d0 = (const float4*)&g_desc[0][0][0];
    const float4* d1 = (const float4*)&g_desc[1][0][0];
    for (int t = tid; t < TS * 16; t += 256) {
        int r = t >> 4, c4 = t & 15;
        float4 a = d0[(size_t)(rb + r) * 16 + c4];
        As[(c4 * 4 + 0) * TS + r] = a.x; As[(c4 * 4 + 1) * TS + r] = a.y;
        As[(c4 * 4 + 2) * TS + r] = a.z; As[(c4 * 4 + 3) * TS + r] = a.w;
        float4 bv = d1[(size_t)(cb + r) * 16 + c4];
        Bs[(c4 * 4 + 0) * TS + r] = bv.x; Bs[(c4 * 4 + 1) * TS + r] = bv.y;
        Bs[(c4 * 4 + 2) * TS + r] = bv.z; Bs[(c4 * 4 + 3) * TS + r] = bv.w;
    }
    __syncthreads();
    int tx = tid & 15, ty = tid >> 4;
    float acc[8][8];
    #pragma unroll
    for (int i = 0; i < 8; i++)
        #pragma unroll
        for (int j = 0; j < 8; j++) acc[i][j] = 0.f;
    #pragma unroll 4
    for (int kk = 0; kk < 64; kk++) {     // strictly ascending k
        const float* Ak = As + kk * TS;
        const float* Bk = Bs + kk * TS;
        float4 a0 = *(const float4*)(Ak + ty * 4);
        float4 a1 = *(const float4*)(Ak + 64 + ty * 4);
        float4 b0 = *(const float4*)(Bk + tx * 4);
        float4 b1 = *(const float4*)(Bk + 64 + tx * 4);
        float av[8] = {a0.x, a0.y, a0.z, a0.w, a1.x, a1.y, a1.z, a1.w};
        float bv[8] = {b0.x, b0.y, b0.z, b0.w, b1.x, b1.y, b1.z, b1.w};
        #pragma unroll
        for (int i = 0; i < 8; i++)
            #pragma unroll
            for (int j = 0; j < 8; j++)
                acc[i][j] = __fmaf_rn(av[i], bv[j], acc[i][j]);
    }
    __syncthreads();
    u64* rowP = (u64*)sh;
    u64* colP = rowP + TS;
    if (tid < TS) { rowP[tid] = 0ull; colP[tid] = 0ull; }
    __syncthreads();
    #pragma unroll
    for (int i = 0; i < 8; i++) {
        int lr = (i < 4) ? (ty * 4 + i) : (64 + ty * 4 + i - 4);
        u64 best = 0ull;
        #pragma unroll
        for (int j = 0; j < 8; j++) {
            int gc = cb + ((j < 4) ? (tx * 4 + j) : (64 + tx * 4 + j - 4));
            u64 pk = ((u64)fkey(acc[i][j]) << 32) | (u64)(0xFFFFFFFFu - (u32)gc);
            if (pk > best) best = pk;
        }
        atomicMax(&rowP[lr], best);
    }
    #pragma unroll
    for (int j = 0; j < 8; j++) {
        int lc = (j < 4) ? (tx * 4 + j) : (64 + tx * 4 + j - 4);
        u64 best = 0ull;
        #pragma unroll
        for (int i = 0; i < 8; i++) {
            int gr = rb + ((i < 4) ? (ty * 4 + i) : (64 + ty * 4 + i - 4));
            u64 pk = ((u64)fkey(acc[i][j]) << 32) | (u64)(0xFFFFFFFFu - (u32)gr);
            if (pk > best) best = pk;
        }
        atomicMax(&colP[lc], best);
    }
    __syncthreads();
    if (tid < TS) {
        atomicMax(&g_rowP[rb + tid], rowP[tid]);
        atomicMax(&g_colP[cb + tid], colP[tid]);
    }
}

__global__ void k_final(float* __restrict__ dout) {
    int k = blockIdx.x * blockDim.x + threadIdx.x;   // exact: 4096
    u64 rp = g_rowP[k];
    float sc = unfkey((u32)(rp >> 32));
    u32 m01 = 0xFFFFFFFFu - (u32)rp;
    u64 cp = g_colP[m01];
    u32 m10 = 0xFFFFFFFFu - (u32)cp;
    bool valid = (m10 == (u32)k) && (sc > 0.1f);
    dout[OFF_MATCH + k] = (float)m01;
    dout[OFF_SCORE + k] = sc;
    dout[OFF_VALID + k] = valid ? 1.f : 0.f;
}

extern "C" void kernel_launch(void* const* d_in, const int* in_sizes, int n_in,
                              void* d_out, int out_size) {
    const float* feats   = (const float*)d_in[0];
    const float* logits  = (const float*)d_in[1];
    const float* heatmap = (const float*)d_in[2];
    float* out = (float*)d_out;

    cudaFuncSetAttribute(k_sim, cudaFuncAttributeMaxDynamicSharedMemorySize, 64 * TS * 2 * 4);

    k_init<<<256, 256>>>();
    k_prep<<<300, 256>>>(logits, feats);
    k_nms<<<2 * NPIX / 320, 320>>>(heatmap, out);
    k_scan<0><<<2, 256>>>();
    k_sel0<<<2 * NPIX / 256, 256>>>();
    k_scan<1><<<2, 256>>>();
    k_sel1<<<dim3(64, 2), 256>>>();
    k_tie<<<2, 256>>>();
    k_rank<<<dim3(K_TOP / 256, 2), 256>>>(out);
    k_desc<<<dim3(K_TOP, 2), 32>>>();
    k_sim<<<dim3(K_TOP / TS, K_TOP / TS), 256, 64 * TS * 2 * 4>>>();
    k_final<<<K_TOP / 256, 256>>>(out);
}

// round 13
// speedup vs baseline: 1.9322x; 1.0608x over previous
#include <cuda_runtime.h>

typedef unsigned int u32;
typedef unsigned long long u64;

extern "C" __device__ float __nv_expf(float);   // libdevice expf (matches XLA)

#define K_TOP 4096
#define W_IMG 640
#define H_IMG 480
#define NPIX (W_IMG * H_IMG)      // 307200
#define WC 80
#define HC 60
#define NC (WC * HC)              // 4800
#define CH 64
#define CAND_MAX 320000

#define OFF_KPTS  0
#define OFF_MATCH 16384
#define OFF_SCORE 20480
#define OFF_VALID 24576
#define OFF_H     28672
#define OFF_R     643072

__device__ float g_Hs[2 * NPIX];
__device__ float g_FS[2 * NPIX];
__device__ float g_nf[2 * CH * NC];
__device__ u32   g_hist[2][2][65536];
__device__ u32   g_coarse[2][2][256];
__device__ u64   g_prefix[2];
__device__ u32   g_krem[2];
__device__ u32   g_cnt[2];
__device__ u32   g_candn[2][2];
__device__ u64   g_cand[2][2][CAND_MAX];
__device__ u64   g_sel[2][K_TOP];
__device__ int   g_topidx[2][K_TOP];
__device__ float g_desc[2][K_TOP][CH];
__device__ u64   g_rowP[K_TOP];
__device__ u64   g_colP[K_TOP];

__device__ __forceinline__ u32 fkey(float f) {
    u32 u = __float_as_uint(f);
    return (u >> 31) ? ~u : (u | 0x80000000u);
}
__device__ __forceinline__ float unfkey(u32 k) {
    return __uint_as_float((k >> 31) ? (k & 0x7FFFFFFFu) : ~k);
}

__device__ __forceinline__ u32 warp_append(u32* counter, u32 mask) {
    int lane = threadIdx.x & 31;
    u32 ldr = __ffs(mask) - 1;
    u32 base = 0;
    if ((u32)lane == ldr) base = atomicAdd(counter, __popc(mask));
    base = __shfl_sync(mask, base, ldr);
    return base + __popc(mask & ((1u << lane) - 1));
}

// aggregated histogram add for fine+coarse (mask = active lanes)
__device__ __forceinline__ void hist_add(u32* fine, u32* coarse, u32 bin, u32 mask) {
    u32 peers = __match_any_sync(mask, bin);
    if ((u32)(__ffs(peers) - 1) == (threadIdx.x & 31u))
        atomicAdd(&fine[bin], __popc(peers));
    u32 cbin = bin >> 8;
    u32 cpeers = __match_any_sync(mask, cbin);
    if ((u32)(__ffs(cpeers) - 1) == (threadIdx.x & 31u))
        atomicAdd(&coarse[cbin], __popc(cpeers));
}

__global__ void k_init() {
    int i = blockIdx.x * blockDim.x + threadIdx.x;
    int st = blockDim.x * gridDim.x;
    u32* h = &g_hist[0][0][0];
    for (int j = i; j < 2 * 2 * 65536; j += st) h[j] = 0;
    u32* c = &g_coarse[0][0][0];
    for (int j = i; j < 2 * 2 * 256; j += st) c[j] = 0;
    for (int j = i; j < K_TOP; j += st) { g_rowP[j] = 0ull; g_colP[j] = 0ull; }
    if (i < 2) {
        g_prefix[i] = 0ull; g_krem[i] = K_TOP; g_cnt[i] = 0;
        g_candn[i][0] = 0; g_candn[i][1] = 0;
    }
}

// fused: blocks 0..149 softmax+shuffle (XLA column-reduce order),
//        blocks 150..299 feats norm (same association). smem-staged coalesced.
__global__ void k_prep(const float* __restrict__ logits,
                       const float* __restrict__ feats) {
    __shared__ float sm[65 * 65 + 65];
    int blk = blockIdx.x;
    int lane = threadIdx.x & 31, wrp = threadIdx.x >> 5;
    if (blk < 150) {
        int b = blk / 75;
        int cellbase = (blk % 75) * 64;
        const float* p = logits + (size_t)b * 65 * NC + cellbase;
        for (int i = threadIdx.x; i < 65 * 64; i += 256) {
            int ch = i >> 6, cl = i & 63;
            sm[ch * 65 + cl] = p[ch * NC + cl];
        }
        __syncthreads();
        float* out = g_Hs + (size_t)b * NPIX;
        #pragma unroll
        for (int s = 0; s < 8; s++) {
            int cell = wrp * 8 + s;
            float x0 = sm[lane * 65 + cell];
            float x1 = sm[(lane + 32) * 65 + cell];
            float x2 = (lane == 0) ? sm[64 * 65 + cell] : __int_as_float(0xff800000);
            float m = fmaxf(fmaxf(x0, x1), x2);
            #pragma unroll
            for (int off = 16; off > 0; off >>= 1)
                m = fmaxf(m, __shfl_xor_sync(0xFFFFFFFFu, m, off));
            float e0 = __nv_expf(__fsub_rn(x0, m));
            float e1 = __nv_expf(__fsub_rn(x1, m));
            float e2 = __nv_expf(__fsub_rn(x2, m));
            float partial = __fadd_rn(__fadd_rn(e0, e1), e2);
            #pragma unroll
            for (int off = 16; off > 0; off >>= 1)
                partial = __fadd_rn(partial, __shfl_down_sync(0xFFFFFFFFu, partial, off));
            float ssum = __shfl_sync(0xFFFFFFFFu, partial, 0);
            int gcell = cellbase + cell;
            int h = gcell / WC, w = gcell % WC;
            int c0 = lane, c1 = lane + 32;
            out[(h * 8 + (c0 >> 3)) * W_IMG + (w * 8 + (c0 & 7))] = __fdiv_rn(e0, ssum);
            out[(h * 8 + (c1 >> 3)) * W_IMG + (w * 8 + (c1 & 7))] = __fdiv_rn(e1, ssum);
        }
    } else {
        int blk2 = blk - 150;
        int b = blk2 / 75;
        int cellbase = (blk2 % 75) * 64;
        float* nrm = sm + 64 * 65;
        const float* f = feats + (size_t)b * CH * NC + cellbase;
        float* o = g_nf + (size_t)b * CH * NC + cellbase;
        for (int i = threadIdx.x; i < 64 * 64; i += 256) {
            int ch = i >> 6, cl = i & 63;
            sm[ch * 65 + cl] = f[ch * NC + cl];
        }
        __syncthreads();
        #pragma unroll
        for (int s = 0; s < 8; s++) {
            int cell = wrp * 8 + s;
            float x0 = sm[lane * 65 + cell];
            float x1 = sm[(lane + 32) * 65 + cell];
            float partial = __fadd_rn(__fmul_rn(x0, x0), __fmul_rn(x1, x1));
            #pragma unroll
            for (int off = 16; off > 0; off >>= 1)
                partial = __fadd_rn(partial, __shfl_down_sync(0xFFFFFFFFu, partial, off));
            if (lane == 0) nrm[cell] = fmaxf(__fsqrt_rn(partial), 1e-12f);
        }
        __syncthreads();
        for (int i = threadIdx.x; i < 64 * 64; i += 256) {
            int ch = i >> 6, cl = i & 63;
            o[ch * NC + cl] = __fdiv_rn(sm[ch * 65 + cl], nrm[cl]);
        }
    }
}

// 5x5 NMS (smem-tiled) + bilinear reliability + level-0 fine+coarse hist
__global__ void k_nms(const float* __restrict__ heatmap, float* __restrict__ dout) {
    __shared__ float tile[5][324];
    int tid = threadIdx.x;                       // 320 threads
    int gid = blockIdx.x * 320 + tid;            // exact: 2*NPIX (1920 blocks)
    int b = gid / NPIX, p = gid % NPIX;
    int oy = p / W_IMG;
    int xbase = p % W_IMG - tid;                 // 0 or 320 (strip base)
    const float* Hs = g_Hs + (size_t)b * NPIX;
    for (int i = tid; i < 5 * 324; i += 320) {
        int rr = i / 324, cc = i % 324;
        int row = oy - 2 + rr, col = xbase - 2 + cc;
        float v = __int_as_float(0xff800000);
        if ((unsigned)row < H_IMG && (unsigned)col < W_IMG)
            v = Hs[row * W_IMG + col];
        tile[rr][cc] = v;
    }
    __syncthreads();
    int ox = xbase + tid;

    float sy = __fsub_rn(__fmul_rn(__fadd_rn((float)oy, 0.5f), 0.125f), 0.5f);
    float sx = __fsub_rn(__fmul_rn(__fadd_rn((float)ox, 0.5f), 0.125f), 0.5f);
    int iy0 = (int)floorf(sy);
    int ix0 = (int)floorf(sx);
    float fy = __fsub_rn(sy, (float)iy0);
    float fx = __fsub_rn(sx, (float)ix0);
    int y0 = iy0 < 0 ? 0 : iy0;
    int y1 = iy0 >= HC - 1 ? HC - 1 : iy0 + 1;
    int x0 = ix0 < 0 ? 0 : ix0;
    int x1 = ix0 >= WC - 1 ? WC - 1 : ix0 + 1;
    float wy0 = iy0 < 0 ? 0.f : (iy0 >= HC - 1 ? 1.f : __fsub_rn(1.f, fy));
    float wy1 = iy0 < 0 ? 1.f : (iy0 >= HC - 1 ? 0.f : fy);
    float wx0 = ix0 < 0 ? 0.f : (ix0 >= WC - 1 ? 1.f : __fsub_rn(1.f, fx));
    float wx1 = ix0 < 0 ? 1.f : (ix0 >= WC - 1 ? 0.f : fx);
    const float* hm = heatmap + (size_t)b * NC;
    float t0 = __fmaf_rn(wx1, hm[y0 * WC + x1], __fmul_rn(wx0, hm[y0 * WC + x0]));
    float t1 = __fmaf_rn(wx1, hm[y1 * WC + x1], __fmul_rn(wx0, hm[y1 * WC + x0]));
    float rel = __fmaf_rn(wy1, t1, __fmul_rn(wy0, t0));

    float x = tile[2][tid + 2];
    float lm = x;
    #pragma unroll
    for (int dy = 0; dy < 5; dy++)
        #pragma unroll
        for (int dx = 0; dx < 5; dx++)
            lm = fmaxf(lm, tile[dy][tid + dx]);
    float fs = (x == lm) ? __fmul_rn(x, rel) : 0.f;
    if (fs == 0.f) fs = 0.f;   // canonicalize -0
    g_FS[gid] = fs;
    dout[OFF_H + gid] = fs;
    dout[OFF_R + gid] = rel;

    u32 bin = fkey(fs) >> 16;
    hist_add(g_hist[0][b], g_coarse[0][b], bin, 0xFFFFFFFFu);
}

// threshold scan: parallel suffix-sum pick (identical integer results)
template <int L>
__global__ void k_scan() {
    int b = blockIdx.x;
    __shared__ u32 bufA[256], bufB[256];
    __shared__ int csel;
    __shared__ u32 krem2s;
    int t = threadIdx.x;
    u32 krem = g_krem[b];

    // --- coarse suffix sum ---
    bufA[t] = g_coarse[L][b][t];
    __syncthreads();
    u32* cur = bufA; u32* nxt = bufB;
    #pragma unroll
    for (int off = 1; off < 256; off <<= 1) {
        u32 v = cur[t] + ((t + off < 256) ? cur[t + off] : 0u);
        __syncthreads();
        nxt[t] = v;
        __syncthreads();
        u32* tmp = cur; cur = nxt; nxt = tmp;
    }
    u32 sufN = (t == 255) ? 0u : cur[t + 1];
    if (cur[t] >= krem && sufN < krem) { csel = t; krem2s = krem - sufN; }
    __syncthreads();
    int cs = csel;
    u32 krem2 = krem2s;
    __syncthreads();

    // --- fine suffix sum (selected 256-bin block) ---
    bufA[t] = g_hist[L][b][cs * 256 + t];
    __syncthreads();
    cur = bufA; nxt = bufB;
    #pragma unroll
    for (int off = 1; off < 256; off <<= 1) {
        u32 v = cur[t] + ((t + off < 256) ? cur[t + off] : 0u);
        __syncthreads();
        nxt[t] = v;
        __syncthreads();
        u32* tmp = cur; cur = nxt; nxt = tmp;
    }
    u32 sufNf = (t == 255) ? 0u : cur[t + 1];
    if (cur[t] >= krem2 && sufNf < krem2) {
        g_krem[b] = krem2 - sufNf;
        g_prefix[b] = (g_prefix[b] << 16) | (u64)(u32)(cs * 256 + t);
    }
}

// full pass: definite -> g_sel; threshold-bin -> cand[0] + level-1 fine+coarse
__global__ void k_sel0() {
    int gid = blockIdx.x * blockDim.x + threadIdx.x;   // exact: 2*NPIX
    int b = gid / NPIX;
    u32 i = gid % NPIX;
    u64 key = ((u64)fkey(g_FS[gid]) << 32) | (u64)(0xFFFFFFFFu - i);
    u32 v0 = (u32)(g_prefix[b] & 0xFFFFu);
    u32 bin = (u32)(key >> 48);
    bool isDef = bin > v0, isCand = bin == v0;
    u32 md = __ballot_sync(0xFFFFFFFFu, isDef);
    if (isDef) {
        u32 pos = warp_append(&g_cnt[b], md);
        if (pos < K_TOP) g_sel[b][pos] = key;
    }
    u32 mc = __ballot_sync(0xFFFFFFFFu, isCand);
    if (isCand) {
        u32 pos = warp_append(&g_candn[b][0], mc);
        if (pos < CAND_MAX) g_cand[b][0][pos] = key;
        u32 bin2 = (u32)(key >> 32) & 0xFFFFu;
        hist_add(g_hist[1][b], g_coarse[1][b], bin2, mc);
    }
}

// level 1 over candidates: definite -> g_sel; exact-fkey ties -> cand[1]
__global__ void k_sel1() {
    int b = blockIdx.y;
    u32 N = g_candn[b][0];
    u32 v1 = (u32)(g_prefix[b] & 0xFFFFu);
    u32 total = (N + 255u) & ~255u;
    u32 t0 = blockIdx.x * blockDim.x + threadIdx.x;
    u32 stride = gridDim.x * blockDim.x;
    for (u32 t = t0; t < total; t += stride) {
        bool valid = t < N;
        u64 key = valid ? g_cand[b][0][t] : 0ull;
        u32 bin = (u32)(key >> 32) & 0xFFFFu;
        bool isDef = valid && (bin > v1);
        bool isTie = valid && (bin == v1);
        u32 md = __ballot_sync(0xFFFFFFFFu, isDef);
        if (isDef) {
            u32 pos = warp_append(&g_cnt[b], md);
            if (pos < K_TOP) g_sel[b][pos] = key;
        }
        u32 mt = __ballot_sync(0xFFFFFFFFu, isTie);
        if (isTie) {
            u32 pos = warp_append(&g_candn[b][1], mt);
            if (pos < CAND_MAX) g_cand[b][1][pos] = key;
        }
    }
}

// ties share exact fkey: take krem largest keys (= smallest indices) by rank
__global__ void k_tie() {
    int b = blockIdx.x;
    u32 N = g_candn[b][1];
    u32 need = g_krem[b];
    for (u32 t = threadIdx.x; t < N; t += 256) {
        u64 key = g_cand[b][1][t];
        u32 r = 0;
        for (u32 j = 0; j < N; j++) r += (g_cand[b][1][j] > key);
        if (r < need) {
            u32 pos = atomicAdd(&g_cnt[b], 1);
            if (pos < K_TOP) g_sel[b][pos] = key;
        }
    }
}

// rank-by-counting (keys unique): rank = #{keys greater}; emit kpts + topidx
__global__ void k_rank(float* __restrict__ dout) {
    int b = blockIdx.y;
    int i = blockIdx.x * 256 + threadIdx.x;
    u64 my = g_sel[b][i];
    __shared__ u64 tile[256];
    int r = 0;
    for (int t = 0; t < K_TOP; t += 256) {
        tile[threadIdx.x] = g_sel[b][t + threadIdx.x];
        __syncthreads();
        #pragma unroll 8
        for (int j = 0; j < 256; j++) r += (tile[j] > my);
        __syncthreads();
    }
    u32 idx = 0xFFFFFFFFu - (u32)my;
    g_topidx[b][r] = (int)idx;
    float x = (float)(idx % W_IMG), y = (float)(idx / W_IMG);
    dout[OFF_KPTS + (size_t)b * K_TOP * 2 + r * 2 + 0] = x;
    dout[OFF_KPTS + (size_t)b * K_TOP * 2 + r * 2 + 1] = y;
}

// grid-sample + renorm: 8 warps/block, one keypoint per warp (same per-warp math)
__global__ void k_desc() {
    int wrp = threadIdx.x >> 5, lane = threadIdx.x & 31;
    int k = blockIdx.x * 8 + wrp, b = blockIdx.y;
    int idx = g_topidx[b][k];
    float xf = (float)(idx % W_IMG), yf = (float)(idx / W_IMG);
    float gx = __fsub_rn(__fmul_rn(__fdiv_rn(xf, 639.f), 2.f), 1.f);
    float gy = __fsub_rn(__fmul_rn(__fdiv_rn(yf, 479.f), 2.f), 1.f);
    float ix = __fmul_rn(__fmul_rn(__fadd_rn(gx, 1.f), 0.5f), 79.f);
    float iy = __fmul_rn(__fmul_rn(__fadd_rn(gy, 1.f), 0.5f), 59.f);
    float ix0f = floorf(ix), iy0f = floorf(iy);
    float wx = __fsub_rn(ix, ix0f), wy = __fsub_rn(iy, iy0f);
    float omx = __fsub_rn(1.f, wx), omy = __fsub_rn(1.f, wy);
    int x0 = min(max((int)ix0f, 0), WC - 1), y0 = min(max((int)iy0f, 0), HC - 1);
    int x1 = min(x0 + 1, WC - 1), y1 = min(y0 + 1, HC - 1);
    int p00 = y0 * WC + x0, p01 = y0 * WC + x1, p10 = y1 * WC + x0, p11 = y1 * WC + x1;
    float v[2];
    #pragma unroll
    for (int t = 0; t < 2; t++) {
        int c = 2 * lane + t;
        const float* f = g_nf + ((size_t)b * CH + c) * NC;
        float t1 = __fmul_rn(__fmul_rn(f[p00], omx), omy);
        float t2 = __fmul_rn(__fmul_rn(f[p01], wx), omy);
        float t3 = __fmul_rn(__fmul_rn(f[p10], omx), wy);
        float t4 = __fmul_rn(__fmul_rn(f[p11], wx), wy);
        v[t] = __fadd_rn(__fadd_rn(__fadd_rn(t1, t2), t3), t4);
    }
    float pr = __fadd_rn(__fmul_rn(v[0], v[0]), __fmul_rn(v[1], v[1]));
    #pragma unroll
    for (int off = 16; off > 0; off >>= 1)
        pr = __fadd_rn(pr, __shfl_down_sync(0xFFFFFFFFu, pr, off));
    float n = fmaxf(__fsqrt_rn(__shfl_sync(0xFFFFFFFFu, pr, 0)), 1e-12f);
    g_desc[b][k][2 * lane + 0] = __fdiv_rn(v[0], n);
    g_desc[b][k][2 * lane + 1] = __fdiv_rn(v[1], n);
}

// sim: VALIDATED fp32 ascending-k FFMA chain; fused row/col argmax. UNCHANGED.
#define TS 128
__global__ void k_sim() {
    extern __shared__ float sh[];
    float* As = sh;             // [64][128] k-major
    float* Bs = sh + 64 * TS;   // [64][128] k-major
    int tid = threadIdx.x;
    int rb = blockIdx.y * TS;
    int cb = blockIdx.x * TS;
    const float4* d0 = (const float4*)&g_desc[0][0][0];
    const float4* d1 = (const float4*)&g_desc[1][0][0];
    for (int t = tid; t < TS * 16; t += 256) {
        int r = t >> 4, c4 = t & 15;
        float4 a = d0[(size_t)(rb + r) * 16 + c4];
        As[(c4 * 4 + 0) * TS + r] = a.x; As[(c4 * 4 + 1) * TS + r] = a.y;
        As[(c4 * 4 + 2) * TS + r] = a.z; As[(c4 * 4 + 3) * TS + r] = a.w;
        float4 bv = d1[(size_t)(cb + r) * 16 + c4];
        Bs[(c4 * 4 + 0) * TS + r] = bv.x; Bs[(c4 * 4 + 1) * TS + r] = bv.y;
        Bs[(c4 * 4 + 2) * TS + r] = bv.z; Bs[(c4 * 4 + 3) * TS + r] = bv.w;
    }
    __syncthreads();
    int tx = tid & 15, ty = tid >> 4;
    float acc[8][8];
    #pragma unroll
    for (int i = 0; i < 8; i++)
        #pragma unroll
        for (int j = 0; j < 8; j++) acc[i][j] = 0.f;
    #pragma unroll 4
    for (int kk = 0; kk < 64; kk++) {     // strictly ascending k
        const float* Ak = As + kk * TS;
        const float* Bk = Bs + kk * TS;
        float4 a0 = *(const float4*)(Ak + ty * 4);
        float4 a1 = *(const float4*)(Ak + 64 + ty * 4);
        float4 b0 = *(const float4*)(Bk + tx * 4);
        float4 b1 = *(const float4*)(Bk + 64 + tx * 4);
        float av[8] = {a0.x, a0.y, a0.z, a0.w, a1.x, a1.y, a1.z, a1.w};
        float bv[8] = {b0.x, b0.y, b0.z, b0.w, b1.x, b1.y, b1.z, b1.w};
        #pragma unroll
        for (int i = 0; i < 8; i++)
            #pragma unroll
            for (int j = 0; j < 8; j++)
                acc[i][j] = __fmaf_rn(av[i], bv[j], acc[i][j]);
    }
    __syncthreads();
    u64* rowP = (u64*)sh;
    u64* colP = rowP + TS;
    if (tid < TS) { rowP[tid] = 0ull; colP[tid] = 0ull; }
    __syncthreads();
    #pragma unroll
    for (int i = 0; i < 8; i++) {
        int lr = (i < 4) ? (ty * 4 + i) : (64 + ty * 4 + i - 4);
        u64 best = 0ull;
        #pragma unroll
        for (int j = 0; j < 8; j++) {
            int gc = cb + ((j < 4) ? (tx * 4 + j) : (64 + tx * 4 + j - 4));
            u64 pk = ((u64)fkey(acc[i][j]) << 32) | (u64)(0xFFFFFFFFu - (u32)gc);
            if (pk > best) best = pk;
        }
        atomicMax(&rowP[lr], best);
    }
    #pragma unroll
    for (int j = 0; j < 8; j++) {
        int lc = (j < 4) ? (tx * 4 + j) : (64 + tx * 4 + j - 4);
        u64 best = 0ull;
        #pragma unroll
        for (int i = 0; i < 8; i++) {
            int gr = rb + ((i < 4) ? (ty * 4 + i) : (64 + ty * 4 + i - 4));
            u64 pk = ((u64)fkey(acc[i][j]) << 32) | (u64)(0xFFFFFFFFu - (u32)gr);
            if (pk > best) best = pk;
        }
        atomicMax(&colP[lc], best);
    }
    __syncthreads();
    if (tid < TS) {
        atomicMax(&g_rowP[rb + tid], rowP[tid]);
        atomicMax(&g_colP[cb + tid], colP[tid]);
    }
}

__global__ void k_final(float* __restrict__ dout) {
    int k = blockIdx.x * blockDim.x + threadIdx.x;   // exact: 4096
    u64 rp = g_rowP[k];
    float sc = unfkey((u32)(rp >> 32));
    u32 m01 = 0xFFFFFFFFu - (u32)rp;
    u64 cp = g_colP[m01];
    u32 m10 = 0xFFFFFFFFu - (u32)cp;
    bool valid = (m10 == (u32)k) && (sc > 0.1f);
    dout[OFF_MATCH + k] = (float)m01;
    dout[OFF_SCORE + k] = sc;
    dout[OFF_VALID + k] = valid ? 1.f : 0.f;
}

extern "C" void kernel_launch(void* const* d_in, const int* in_sizes, int n_in,
                              void* d_out, int out_size) {
    const float* feats   = (const float*)d_in[0];
    const float* logits  = (const float*)d_in[1];
    const float* heatmap = (const float*)d_in[2];
    float* out = (float*)d_out;

    cudaFuncSetAttribute(k_sim, cudaFuncAttributeMaxDynamicSharedMemorySize, 64 * TS * 2 * 4);

    k_init<<<256, 256>>>();
    k_prep<<<300, 256>>>(logits, feats);
    k_nms<<<2 * NPIX / 320, 320>>>(heatmap, out);
    k_scan<0><<<2, 256>>>();
    k_sel0<<<2 * NPIX / 256, 256>>>();
    k_scan<1><<<2, 256>>>();
    k_sel1<<<dim3(64, 2), 256>>>();
    k_tie<<<2, 256>>>();
    k_rank<<<dim3(K_TOP / 256, 2), 256>>>(out);
    k_desc<<<dim3(K_TOP / 8, 2), 256>>>();
    k_sim<<<dim3(K_TOP / TS, K_TOP / TS), 256, 64 * TS * 2 * 4>>>();
    k_final<<<K_TOP / 256, 256>>>(out);
}